// round 11
// baseline (speedup 1.0000x reference)
#include <cuda_runtime.h>
#include <cuda_bf16.h>
#include <math.h>
#include <stdint.h>

// ---------------------------------------------------------------------------
// PoincareLinear via tcgen05 bf16 split GEMM (sm_103a) + SIMT fallback body.
//   dot = x_hi@w_hi + x_hi@w_lo + x_lo@w_hi   (K_eff = 3*1024)
//   Tiles pre-swizzled tile-major in global.
//   R11: each 64KB stage loaded by 16 lanes of warp 0 (one 4KB bulk copy per
//   lane, shared tx barrier) -- tests whether the bulk engine serializes ops
//   per issuing thread. 3 stages, prefetch distance 2, commit-gated reuse.
// ---------------------------------------------------------------------------

#if defined(__CUDA_ARCH_FEAT_SM103_ALL) || defined(__CUDA_ARCH_FEAT_SM100_ALL) || \
    defined(__CUDA_ARCH_SPECIFIC__) || defined(__CUDA_ARCH_FAMILY_SPECIFIC__)
#define HAS_TCGEN05 1
#else
#define HAS_TCGEN05 0
#endif

#define N_MAX   32768
#define IN_MAX  1024
#define OUT_MAX 1024
#define TILE_BYTES 32768u            // 256 rows x 128 B

// tile-major, pre-swizzled: blob[(rowblock*16 + kchunk)*32KB + SW128(r*128+j*16)]
__device__ uint8_t g_xhi_t[(size_t)N_MAX * IN_MAX * 2];
__device__ uint8_t g_xlo_t[(size_t)N_MAX * IN_MAX * 2];
__device__ uint8_t g_whi_t[(size_t)OUT_MAX * IN_MAX * 2];
__device__ uint8_t g_wlo_t[(size_t)OUT_MAX * IN_MAX * 2];
__device__ float g_colscale[OUT_MAX];
__device__ float g_coshb[OUT_MAX];
__device__ float g_sinhb[OUT_MAX];
__device__ float g_cx2[N_MAX];
__device__ float g_ysq_part[(size_t)N_MAX * 4];

constexpr uint64_t kSmemDescBaseSW128 =
    (uint64_t(2) << 61) | (uint64_t(1) << 46) | (uint64_t(64) << 32) | (uint64_t(1) << 16);

// ---------------- generic helpers -------------------------------------------
__device__ __forceinline__ uint32_t smem_u32(const void* p) {
    uint32_t a;
    asm("{ .reg .u64 t; cvta.to.shared.u64 t, %1; cvt.u32.u64 %0, t; }"
        : "=r"(a) : "l"(p));
    return a;
}
#define SW128(off) ((off) ^ (((off) >> 3) & 0x70))

__device__ __forceinline__ float block_reduce_sum(float v) {
    __shared__ float red[32];
    int lane = threadIdx.x & 31, wid = threadIdx.x >> 5;
    #pragma unroll
    for (int o = 16; o > 0; o >>= 1) v += __shfl_down_sync(0xffffffff, v, o);
    if (lane == 0) red[wid] = v;
    __syncthreads();
    int nw = (blockDim.x + 31) >> 5;
    v = (threadIdx.x < nw) ? red[threadIdx.x] : 0.f;
    if (wid == 0)
        #pragma unroll
        for (int o = 16; o > 0; o >>= 1) v += __shfl_down_sync(0xffffffff, v, o);
    return v;
}

__device__ __forceinline__ uint32_t pack_bf16x2(float a, float b) {
    __nv_bfloat16 ha = __float2bfloat16(a), hb = __float2bfloat16(b);
    return ((uint32_t)__bfloat16_as_ushort(hb) << 16) | __bfloat16_as_ushort(ha);
}

#if HAS_TCGEN05
// ---------------- tcgen05 / mbarrier / bulk-copy wrappers --------------------
__device__ __forceinline__ uint64_t make_desc(uint32_t addr) {
    return kSmemDescBaseSW128 | ((uint64_t)(addr >> 4) & 0x3FFF);
}
__device__ __forceinline__ void mbar_init(uint32_t a, uint32_t cnt) {
    asm volatile("mbarrier.init.shared.b64 [%0], %1;" :: "r"(a), "r"(cnt) : "memory");
}
__device__ __forceinline__ void mbar_expect_tx(uint32_t a, uint32_t bytes) {
    asm volatile("mbarrier.arrive.expect_tx.shared.b64 _, [%0], %1;"
                 :: "r"(a), "r"(bytes) : "memory");
}
__device__ __forceinline__ void mbar_wait(uint32_t a, uint32_t parity) {
    uint32_t done;
    asm volatile("{ .reg .pred p; mbarrier.try_wait.parity.acquire.cta.shared::cta.b64 p, [%1], %2;"
                 " selp.b32 %0,1,0,p; }" : "=r"(done) : "r"(a), "r"(parity) : "memory");
    if (!done) {
        asm volatile("{ .reg .pred P1; WL%=:"
                     " mbarrier.try_wait.parity.acquire.cta.shared::cta.b64 P1, [%0], %1, 0x989680;"
                     " @P1 bra.uni WD%=; bra.uni WL%=; WD%=: }"
                     :: "r"(a), "r"(parity) : "memory");
    }
}
__device__ __forceinline__ void bulk_g2s(uint32_t dst, const void* src, uint32_t bytes,
                                         uint32_t mbar) {
    asm volatile("cp.async.bulk.shared::cta.global.mbarrier::complete_tx::bytes"
                 " [%0], [%1], %2, [%3];"
                 :: "r"(dst), "l"(src), "r"(bytes), "r"(mbar) : "memory");
}
__device__ __forceinline__ void tc_alloc(uint32_t smem_dst, uint32_t ncols) {
    asm volatile("tcgen05.alloc.cta_group::1.sync.aligned.shared::cta.b32 [%0], %1;"
                 :: "r"(smem_dst), "r"(ncols) : "memory");
}
__device__ __forceinline__ void tc_dealloc(uint32_t tmem, uint32_t ncols) {
    asm volatile("tcgen05.dealloc.cta_group::1.sync.aligned.b32 %0, %1;" :: "r"(tmem), "r"(ncols));
}
__device__ __forceinline__ void tc_relinquish() {
    asm volatile("tcgen05.relinquish_alloc_permit.cta_group::1.sync.aligned;");
}
__device__ __forceinline__ void tc_commit(uint32_t mbar) {
    asm volatile("tcgen05.commit.cta_group::1.mbarrier::arrive::one.shared::cluster.b64 [%0];"
                 :: "r"(mbar) : "memory");
}
__device__ __forceinline__ void mma_f16_ss(uint32_t d, uint64_t ad, uint64_t bd,
                                           uint32_t idesc, bool acc) {
    uint32_t en = acc ? 1u : 0u;
    asm volatile("{ .reg .pred p; setp.ne.u32 p, %4, 0;"
                 " tcgen05.mma.cta_group::1.kind::f16 [%0], %1, %2, %3, {%5,%5,%5,%5}, p; }"
                 :: "r"(d), "l"(ad), "l"(bd), "r"(idesc), "r"(en), "r"(0u) : "memory");
}
#define TC_LD_X32(r, addr) \
    asm volatile("tcgen05.ld.sync.aligned.32x32b.x32.b32 " \
        "{%0,%1,%2,%3,%4,%5,%6,%7,%8,%9,%10,%11,%12,%13,%14,%15," \
        "%16,%17,%18,%19,%20,%21,%22,%23,%24,%25,%26,%27,%28,%29,%30,%31}, [%32];" \
        : "=r"((r)[0]),"=r"((r)[1]),"=r"((r)[2]),"=r"((r)[3]),"=r"((r)[4]),"=r"((r)[5]), \
          "=r"((r)[6]),"=r"((r)[7]),"=r"((r)[8]),"=r"((r)[9]),"=r"((r)[10]),"=r"((r)[11]), \
          "=r"((r)[12]),"=r"((r)[13]),"=r"((r)[14]),"=r"((r)[15]),"=r"((r)[16]),"=r"((r)[17]), \
          "=r"((r)[18]),"=r"((r)[19]),"=r"((r)[20]),"=r"((r)[21]),"=r"((r)[22]),"=r"((r)[23]), \
          "=r"((r)[24]),"=r"((r)[25]),"=r"((r)[26]),"=r"((r)[27]),"=r"((r)[28]),"=r"((r)[29]), \
          "=r"((r)[30]),"=r"((r)[31]) : "r"(addr))
#define TC_WAIT_LD()  asm volatile("tcgen05.wait::ld.sync.aligned;" ::: "memory")
#define TC_FENCE_AFTER()  asm volatile("tcgen05.fence::after_thread_sync;" ::: "memory")
#define TC_FENCE_BEFORE() asm volatile("tcgen05.fence::before_thread_sync;" ::: "memory")
#endif // HAS_TCGEN05

// ---------------- prep: colscale + cosh/sinh(2 rc b), block per column -------
__global__ void prep_kernel(const float* __restrict__ w, const float* __restrict__ bias,
                            const float* __restrict__ c_ptr, int IN, int OUT) {
    int o = blockIdx.x;
    float s = 0.f;
    for (int i = threadIdx.x; i < IN; i += blockDim.x) {
        float v = w[(size_t)i * OUT + o];
        s = fmaf(v, v, s);
    }
    float tot = block_reduce_sum(s);
    if (threadIdx.x == 0) {
        g_colscale[o] = 1.0f / fmaxf(sqrtf(tot), 1e-15f);
        float rc = sqrtf(c_ptr[0]);
        float d = 2.0f * rc * bias[o];
        g_coshb[o] = coshf(d);
        g_sinhb[o] = sinhf(d);
    }
}

// ---------------- w -> transposed, scaled, bf16 split, tile-major swizzled ---
__global__ void convert_w_kernel(const float* __restrict__ w, int IN, int OUT) {
    __shared__ float t[32][33];
    int n0 = blockIdx.x * 32, k0 = blockIdx.y * 32;
    int tx = threadIdx.x, ty = threadIdx.y;
    t[ty][tx] = w[(size_t)(k0 + ty) * OUT + n0 + tx];   // t[k_local][n_local]
    __syncthreads();
    if (tx < 4) {
        int n = n0 + ty;
        float cs = g_colscale[n];
        uint32_t hi4[4], lo4[4];
        #pragma unroll
        for (int p = 0; p < 4; ++p) {
            float a = t[tx * 8 + p * 2 + 0][ty] * cs;
            float b = t[tx * 8 + p * 2 + 1][ty] * cs;
            __nv_bfloat16 ha = __float2bfloat16(a), hb = __float2bfloat16(b);
            float ra = a - __bfloat162float(ha), rb = b - __bfloat162float(hb);
            hi4[p] = ((uint32_t)__bfloat16_as_ushort(hb) << 16) | __bfloat16_as_ushort(ha);
            lo4[p] = pack_bf16x2(ra, rb);
        }
        int k = k0 + tx * 8;
        int nb = n >> 8, kc = k >> 6, j = (k >> 3) & 7;
        size_t base = ((size_t)(nb * 16 + kc)) * TILE_BYTES
                    + SW128((uint32_t)((n & 255) * 128 + j * 16));
        *(uint4*)(g_whi_t + base) = make_uint4(hi4[0], hi4[1], hi4[2], hi4[3]);
        *(uint4*)(g_wlo_t + base) = make_uint4(lo4[0], lo4[1], lo4[2], lo4[3]);
    }
}

// ---------------- x -> bf16 hi/lo tile-major swizzled, fused cx2 -------------
__global__ void convert_x_kernel(const float* __restrict__ x,
                                 const float* __restrict__ c_ptr, int IN) {
    int row = blockIdx.x;
    int t = threadIdx.x;                 // 128 threads, 8 elements each
    if (t < 4) g_ysq_part[(size_t)row * 4 + t] = 0.f;
    const float4* xr = (const float4*)(x + (size_t)row * IN) + t * 2;
    float4 v0 = xr[0], v1 = xr[1];
    float s = v0.x*v0.x + v0.y*v0.y + v0.z*v0.z + v0.w*v0.w
            + v1.x*v1.x + v1.y*v1.y + v1.z*v1.z + v1.w*v1.w;
    float e[8] = {v0.x, v0.y, v0.z, v0.w, v1.x, v1.y, v1.z, v1.w};
    uint32_t hi4[4], lo4[4];
    #pragma unroll
    for (int p = 0; p < 4; ++p) {
        float a = e[p*2], b = e[p*2+1];
        __nv_bfloat16 ha = __float2bfloat16(a), hb = __float2bfloat16(b);
        float ra = a - __bfloat162float(ha), rb = b - __bfloat162float(hb);
        hi4[p] = ((uint32_t)__bfloat16_as_ushort(hb) << 16) | __bfloat16_as_ushort(ha);
        lo4[p] = pack_bf16x2(ra, rb);
    }
    int kc = t >> 3, j = t & 7;
    int rb = row >> 8, r = row & 255;
    size_t base = ((size_t)(rb * 16 + kc)) * TILE_BYTES
                + SW128((uint32_t)(r * 128 + j * 16));
    *(uint4*)(g_xhi_t + base) = make_uint4(hi4[0], hi4[1], hi4[2], hi4[3]);
    *(uint4*)(g_xlo_t + base) = make_uint4(lo4[0], lo4[1], lo4[2], lo4[3]);
    float tot = block_reduce_sum(s);
    if (threadIdx.x == 0) g_cx2[row] = c_ptr[0] * tot;
}

// ---------------- GEMM + fused Poincare epilogue -----------------------------
#define MT 256
#define NT 256
#define IDESC ((1u<<4) | (1u<<7) | (1u<<10) | ((NT/8u)<<17) | (8u<<24))

#define OFF_TMEM 0u
#define OFF_MBF  8u                         // full barriers: 8,16,24
#define OFF_MBE  32u                        // empty barriers: 32,40,48
#define OFF_PAR  64u                        // 3 * NT floats
#define OFF_T    4096u
#define ASZ      (MT * 128u)                // 32 KB
#define BSZ      (NT * 128u)                // 32 KB
#define STAGE    (ASZ + BSZ)                // 64 KB
#define SMEM_BYTES (OFF_T + 3u * STAGE)     // 200704

__global__ __launch_bounds__(256, 1)
void gemm_tc_kernel(const float* __restrict__ X, const float* __restrict__ W,
                    const float* __restrict__ wgp, const float* __restrict__ c_ptr,
                    float* __restrict__ out, int Nrows, int IN, int OUT) {
    extern __shared__ char smem[];
#if HAS_TCGEN05
    const uint32_t sb = smem_u32(smem);
    const int tid = threadIdx.x;
    const int wid = tid >> 5, lane = tid & 31;
    const int brow = blockIdx.y * MT, bcol = blockIdx.x * NT;
    const int nchunk = 48;

    if (wid == 0) { tc_alloc(sb + OFF_TMEM, 512); tc_relinquish(); }
    if (tid == 0) {
        #pragma unroll
        for (int s = 0; s < 3; ++s) {
            mbar_init(sb + OFF_MBF + 8u * s, 1);
            mbar_init(sb + OFF_MBE + 8u * s, 1);
        }
    }
    float* chb = (float*)(smem + OFF_PAR);
    float* shb = chb + NT;
    float* g2s = shb + NT;
    if (tid < NT) {
        int o = bcol + tid;
        chb[tid] = g_coshb[o];
        shb[tid] = g_sinhb[o];
        g2s[tid] = 2.0f * wgp[o];
    }
    __syncthreads();
    uint32_t tmem;
    asm volatile("ld.shared.b32 %0, [%1];" : "=r"(tmem) : "r"(sb + OFF_TMEM));

    if (wid == 0) {
        // chunk -> source blobs (tile-major, pre-swizzled)
        auto srcA = [&](int c) -> const uint8_t* {
            int seg = c >> 4, kc = c & 15;
            const uint8_t* p = (seg == 2) ? g_xlo_t : g_xhi_t;
            return p + ((size_t)(blockIdx.y * 16 + kc)) * TILE_BYTES;
        };
        auto srcB = [&](int c) -> const uint8_t* {
            int seg = c >> 4, kc = c & 15;
            const uint8_t* p = (seg == 1) ? g_wlo_t : g_whi_t;
            return p + ((size_t)(blockIdx.x * 16 + kc)) * TILE_BYTES;
        };
        // 16 lanes each issue one 4KB bulk copy (lanes 0-7: A, 8-15: B),
        // all completing on the stage's FULL barrier.
        auto load_chunk = [&](int c, int s) {
            uint32_t fb = sb + OFF_MBF + 8u * (uint32_t)s;
            uint32_t base = sb + OFF_T + (uint32_t)s * STAGE;
            if (lane == 0) mbar_expect_tx(fb, 2u * TILE_BYTES);
            __syncwarp();
            if (lane < 16) {
                const uint8_t* src = (lane < 8)
                    ? srcA(c) + (uint32_t)lane * 4096u
                    : srcB(c) + (uint32_t)(lane - 8) * 4096u;
                uint32_t dst = base + (uint32_t)lane * 4096u;   // A then B halves
                bulk_g2s(dst, src, 4096u, fb);
            }
        };
        load_chunk(0, 0);
        load_chunk(1, 1);

        for (int c = 0; c < nchunk; ++c) {
            const int s = c % 3;
            mbar_wait(sb + OFF_MBF + 8u * (uint32_t)s, (uint32_t)((c / 3) & 1));
            if (lane == 0) {
                const uint32_t Aoff = sb + OFF_T + (uint32_t)s * STAGE;
                uint64_t ad = make_desc(Aoff);
                uint64_t bd = make_desc(Aoff + ASZ);
                #pragma unroll
                for (int k = 0; k < 4; ++k) {
                    bool acc = (c > 0) || (k > 0);
                    mma_f16_ss(tmem,       ad + k * 2,        bd + k * 2, IDESC, acc);
                    mma_f16_ss(tmem + 256, ad + 1024 + k * 2, bd + k * 2, IDESC, acc);
                }
                tc_commit(sb + OFF_MBE + 8u * (uint32_t)s);
            }
            if (c + 2 < nchunk) {
                const int s2 = (c + 2) % 3;      // stage last used by chunk c-1
                if (c >= 1)
                    mbar_wait(sb + OFF_MBE + 8u * (uint32_t)s2,
                              (uint32_t)(((c - 1) / 3) & 1));
                load_chunk(c + 2, s2);
            }
        }
        // last commits: stage commit index nchunk/3-1 = 15 -> parity 1
        mbar_wait(sb + OFF_MBE + 0, 1);
        mbar_wait(sb + OFF_MBE + 8, 1);
        mbar_wait(sb + OFF_MBE + 16, 1);
    }
    __syncthreads();
    TC_FENCE_AFTER();

    // ---- epilogue: 8 warps; half = wid>>2 selects M-half / TMEM 256-col bank
    const float rc = sqrtf(c_ptr[0]);
    const float invrc = 1.0f / rc;
    const int half = wid >> 2, sub = wid & 3;
    const int row = brow + half * 128 + sub * 32 + lane;
    const float cx2 = g_cx2[row];
    const float invd = 1.0f / fmaxf(1.0f - cx2, 1e-15f);
    const float onep = 1.0f + cx2;
    const float two_rc = 2.0f * rc;
    float ysq = 0.f;

    #pragma unroll
    for (int cc = 0; cc < 4; ++cc) {
        const int cb = cc * 64;
        uint32_t d[64];
        TC_LD_X32(d, tmem + half * 256 + cb);
        TC_LD_X32(d + 32, tmem + half * 256 + cb + 32);
        TC_WAIT_LD();
        float* orow = out + (size_t)row * OUT + bcol + cb;
        #pragma unroll
        for (int j = 0; j < 64; j += 4) {
            float yv[4];
            #pragma unroll
            for (int q = 0; q < 4; ++q) {
                int col = cb + j + q;
                float dot = __uint_as_float(d[j + q]);
                float num = fmaf(two_rc * dot, chb[col], -onep * shb[col]);
                float u = num * invd;
                // sinh(g*asinh(u)) = sign(u) * (t^g - t^-g)/2, t = sqrt(u^2+1)+|u|
                float sq = sqrtf(fmaf(u, u, 1.0f));
                float t  = sq + fabsf(u);
                float lt = __logf(t);
                float p  = __expf(g2s[col] * lt);
                float mag = (p - __fdividef(1.0f, p)) * 0.5f * invrc;
                float y = copysignf(mag, u);
                ysq = fmaf(y, y, ysq);
                yv[q] = y;
            }
            *(float4*)(orow + j) = make_float4(yv[0], yv[1], yv[2], yv[3]);
        }
    }
    g_ysq_part[(size_t)row * 4 + blockIdx.x] = ysq;

    TC_FENCE_BEFORE();
    __syncthreads();
    if (wid == 0) tc_dealloc(tmem, 512);

#else  // ------------- SIMT fallback (non-'a' PTX stage; never runs on GB300) -
    float (*As)[128] = (float(*)[128])(smem);
    float (*Bs)[128] = (float(*)[128])(smem + 16 * 128 * 4);

    const int tid = threadIdx.x;
    const int tx = tid & 15, ty = tid >> 4;
    const float cval = c_ptr[0];
    const float rc = sqrtf(cval);
    const float invrc = 1.0f / rc;

    for (int mh = 0; mh < 2; ++mh) {
        const int brow = blockIdx.y * MT + mh * 128;
        for (int nh = 0; nh < 2; ++nh) {
            const int bcol = blockIdx.x * NT + nh * 128;
            float acc[8][8];
            #pragma unroll
            for (int i = 0; i < 8; ++i)
                #pragma unroll
                for (int j = 0; j < 8; ++j) acc[i][j] = 0.f;

            for (int kt = 0; kt < IN; kt += 16) {
                #pragma unroll
                for (int l = 0; l < 2; ++l) {
                    int idx = tid + l * 256;
                    int r = idx >> 2, c4 = (idx & 3) << 2;
                    float4 v = *(const float4*)(X + (size_t)(brow + r) * IN + kt + c4);
                    As[c4 + 0][r] = v.x; As[c4 + 1][r] = v.y;
                    As[c4 + 2][r] = v.z; As[c4 + 3][r] = v.w;
                }
                #pragma unroll
                for (int l = 0; l < 2; ++l) {
                    int idx = tid + l * 256;
                    int r = idx >> 5, c4 = (idx & 31) << 2;
                    *(float4*)(&Bs[r][c4]) =
                        *(const float4*)(W + (size_t)(kt + r) * OUT + bcol + c4);
                }
                __syncthreads();
                #pragma unroll
                for (int k = 0; k < 16; ++k) {
                    float a[8], b[8];
                    #pragma unroll
                    for (int q = 0; q < 8; ++q) a[q] = As[k][ty * 8 + q];
                    #pragma unroll
                    for (int q = 0; q < 8; ++q) b[q] = Bs[k][tx * 8 + q];
                    #pragma unroll
                    for (int i = 0; i < 8; ++i)
                        #pragma unroll
                        for (int j = 0; j < 8; ++j)
                            acc[i][j] = fmaf(a[i], b[j], acc[i][j]);
                }
                __syncthreads();
            }
            #pragma unroll
            for (int i = 0; i < 8; ++i) {
                int n = brow + ty * 8 + i;
                float cx2 = g_cx2[n];
                float invd = 1.0f / fmaxf(1.0f - cx2, 1e-15f);
                float onep = 1.0f + cx2;
                float y[8];
                float ysq = 0.f;
                #pragma unroll
                for (int j = 0; j < 8; ++j) {
                    int o = bcol + tx * 8 + j;
                    float num = 2.0f * rc * acc[i][j] * g_colscale[o] * g_coshb[o]
                                - onep * g_sinhb[o];
                    float a = 2.0f * wgp[o] * asinhf(num * invd);
                    y[j] = sinhf(a) * invrc;
                    ysq = fmaf(y[j], y[j], ysq);
                }
                atomicAdd(&g_ysq_part[(size_t)n * 4 + blockIdx.x], ysq);
                float* orow = out + (size_t)n * OUT + bcol + tx * 8;
                *(float4*)(orow)     = make_float4(y[0], y[1], y[2], y[3]);
                *(float4*)(orow + 4) = make_float4(y[4], y[5], y[6], y[7]);
            }
            __syncthreads();
        }
    }
#endif
}

// ---------------- rescale: gyro-half map + ball projection -------------------
__global__ void rescale_kernel(float* __restrict__ out,
                               const float* __restrict__ c_ptr, int OUT) {
    int row = blockIdx.x;
    float tot = g_ysq_part[(size_t)row * 4 + 0] + g_ysq_part[(size_t)row * 4 + 1]
              + g_ysq_part[(size_t)row * 4 + 2] + g_ysq_part[(size_t)row * 4 + 3];
    float c = c_ptr[0];
    float denom = 1.0f + sqrtf(1.0f + c * tot);
    float scale = 1.0f / denom;
    float norm = fmaxf(sqrtf(tot) * scale, 1e-15f);
    float kk = -c;
    float maxnorm = (1.0f - 0.004f) * rsqrtf(fmaxf(fabsf(kk), 1e-15f));
    if (!(kk < 0.f)) maxnorm = 1e15f;
    if (norm > maxnorm) scale *= maxnorm / norm;

    float4* yr = (float4*)(out + (size_t)row * OUT);
    int n4 = OUT >> 2;
    for (int i = threadIdx.x; i < n4; i += blockDim.x) {
        float4 v = yr[i];
        v.x *= scale; v.y *= scale; v.z *= scale; v.w *= scale;
        yr[i] = v;
    }
}

// ---------------------------------------------------------------------------
extern "C" void kernel_launch(void* const* d_in, const int* in_sizes, int n_in,
                              void* d_out, int out_size) {
    const float* x    = (const float*)d_in[0];
    const float* w    = (const float*)d_in[1];
    const float* wg   = (const float*)d_in[2];
    const float* bias = (const float*)d_in[3];
    const float* c    = (const float*)d_in[4];
    float* out = (float*)d_out;

    int OUT = in_sizes[2];
    int IN  = in_sizes[1] / OUT;
    int N   = in_sizes[0] / IN;

    static int smem_set = 0;
    if (!smem_set) {
        cudaFuncSetAttribute(gemm_tc_kernel, cudaFuncAttributeMaxDynamicSharedMemorySize,
                             SMEM_BYTES);
        smem_set = 1;
    }

    prep_kernel<<<OUT, 256>>>(w, bias, c, IN, OUT);
    convert_w_kernel<<<dim3(OUT / 32, IN / 32), dim3(32, 32)>>>(w, IN, OUT);
    convert_x_kernel<<<N, 128>>>(x, c, IN);
    dim3 grid(OUT / NT, N / MT);
    gemm_tc_kernel<<<grid, 256, SMEM_BYTES>>>(x, w, wg, c, out, N, IN, OUT);
    rescale_kernel<<<N, 256>>>(out, c, OUT);
}

// round 12
// speedup vs baseline: 1.1449x; 1.1449x over previous
#include <cuda_runtime.h>
#include <cuda_bf16.h>
#include <math.h>
#include <stdint.h>

// ---------------------------------------------------------------------------
// PoincareLinear via tcgen05 bf16 split GEMM (sm_103a) + SIMT fallback body.
//   dot = x_hi@w_hi + x_hi@w_lo + x_lo@w_hi   (K_eff = 3*1024)
//   R12: 2 CTAs/SM. Per-CTA tile 128x256, KC=32 (SW64 swizzle, 64B rows),
//   4 stages x 24KB (96KB smem), prefetch distance 3, TMEM 256 cols/CTA.
//   Tiles pre-swizzled SW64 tile-major in global; one bulk-copy pair/chunk.
// ---------------------------------------------------------------------------

#if defined(__CUDA_ARCH_FEAT_SM103_ALL) || defined(__CUDA_ARCH_FEAT_SM100_ALL) || \
    defined(__CUDA_ARCH_SPECIFIC__) || defined(__CUDA_ARCH_FAMILY_SPECIFIC__)
#define HAS_TCGEN05 1
#else
#define HAS_TCGEN05 0
#endif

#define N_MAX   32768
#define IN_MAX  1024
#define OUT_MAX 1024
#define A_TILE  8192u                // 128 rows x 64 B (KC=32)
#define B_TILE  16384u               // 256 rows x 64 B

// tile-major, pre-SW64-swizzled blobs:
//   X: tile(rb,kc) at (rb*32+kc)*A_TILE,  rb = row>>7,  kc = k>>5
//   W: tile(nb,kc) at (nb*32+kc)*B_TILE,  nb = n>>8,    kc = k>>5
__device__ uint8_t g_xhi_t[(size_t)N_MAX * IN_MAX * 2];
__device__ uint8_t g_xlo_t[(size_t)N_MAX * IN_MAX * 2];
__device__ uint8_t g_whi_t[(size_t)OUT_MAX * IN_MAX * 2];
__device__ uint8_t g_wlo_t[(size_t)OUT_MAX * IN_MAX * 2];
__device__ float g_colscale[OUT_MAX];
__device__ float g_coshb[OUT_MAX];
__device__ float g_sinhb[OUT_MAX];
__device__ float g_cx2[N_MAX];
__device__ float g_ysq_part[(size_t)N_MAX * 4];

// SW64 descriptor: layout=4, version=1 (Blackwell), SBO=32 (512B/8-row group),
// LBO=1 (16B inner stride).
constexpr uint64_t kSmemDescBaseSW64 =
    (uint64_t(4) << 61) | (uint64_t(1) << 46) | (uint64_t(32) << 32) | (uint64_t(1) << 16);

// ---------------- generic helpers -------------------------------------------
__device__ __forceinline__ uint32_t smem_u32(const void* p) {
    uint32_t a;
    asm("{ .reg .u64 t; cvta.to.shared.u64 t, %1; cvt.u32.u64 %0, t; }"
        : "=r"(a) : "l"(p));
    return a;
}
#define SW64(off) ((off) ^ (((off) >> 3) & 0x30))

__device__ __forceinline__ float block_reduce_sum(float v) {
    __shared__ float red[32];
    int lane = threadIdx.x & 31, wid = threadIdx.x >> 5;
    #pragma unroll
    for (int o = 16; o > 0; o >>= 1) v += __shfl_down_sync(0xffffffff, v, o);
    if (lane == 0) red[wid] = v;
    __syncthreads();
    int nw = (blockDim.x + 31) >> 5;
    v = (threadIdx.x < nw) ? red[threadIdx.x] : 0.f;
    if (wid == 0)
        #pragma unroll
        for (int o = 16; o > 0; o >>= 1) v += __shfl_down_sync(0xffffffff, v, o);
    return v;
}

__device__ __forceinline__ uint32_t pack_bf16x2(float a, float b) {
    __nv_bfloat16 ha = __float2bfloat16(a), hb = __float2bfloat16(b);
    return ((uint32_t)__bfloat16_as_ushort(hb) << 16) | __bfloat16_as_ushort(ha);
}

#if HAS_TCGEN05
// ---------------- tcgen05 / mbarrier / bulk-copy wrappers --------------------
__device__ __forceinline__ uint64_t make_desc64(uint32_t addr) {
    return kSmemDescBaseSW64 | ((uint64_t)(addr >> 4) & 0x3FFF);
}
__device__ __forceinline__ void mbar_init(uint32_t a, uint32_t cnt) {
    asm volatile("mbarrier.init.shared.b64 [%0], %1;" :: "r"(a), "r"(cnt) : "memory");
}
__device__ __forceinline__ void mbar_expect_tx(uint32_t a, uint32_t bytes) {
    asm volatile("mbarrier.arrive.expect_tx.shared.b64 _, [%0], %1;"
                 :: "r"(a), "r"(bytes) : "memory");
}
__device__ __forceinline__ void mbar_wait(uint32_t a, uint32_t parity) {
    uint32_t done;
    asm volatile("{ .reg .pred p; mbarrier.try_wait.parity.acquire.cta.shared::cta.b64 p, [%1], %2;"
                 " selp.b32 %0,1,0,p; }" : "=r"(done) : "r"(a), "r"(parity) : "memory");
    if (!done) {
        asm volatile("{ .reg .pred P1; WL%=:"
                     " mbarrier.try_wait.parity.acquire.cta.shared::cta.b64 P1, [%0], %1, 0x989680;"
                     " @P1 bra.uni WD%=; bra.uni WL%=; WD%=: }"
                     :: "r"(a), "r"(parity) : "memory");
    }
}
__device__ __forceinline__ void bulk_g2s(uint32_t dst, const void* src, uint32_t bytes,
                                         uint32_t mbar) {
    asm volatile("cp.async.bulk.shared::cta.global.mbarrier::complete_tx::bytes"
                 " [%0], [%1], %2, [%3];"
                 :: "r"(dst), "l"(src), "r"(bytes), "r"(mbar) : "memory");
}
__device__ __forceinline__ void tc_alloc(uint32_t smem_dst, uint32_t ncols) {
    asm volatile("tcgen05.alloc.cta_group::1.sync.aligned.shared::cta.b32 [%0], %1;"
                 :: "r"(smem_dst), "r"(ncols) : "memory");
}
__device__ __forceinline__ void tc_dealloc(uint32_t tmem, uint32_t ncols) {
    asm volatile("tcgen05.dealloc.cta_group::1.sync.aligned.b32 %0, %1;" :: "r"(tmem), "r"(ncols));
}
__device__ __forceinline__ void tc_relinquish() {
    asm volatile("tcgen05.relinquish_alloc_permit.cta_group::1.sync.aligned;");
}
__device__ __forceinline__ void tc_commit(uint32_t mbar) {
    asm volatile("tcgen05.commit.cta_group::1.mbarrier::arrive::one.shared::cluster.b64 [%0];"
                 :: "r"(mbar) : "memory");
}
__device__ __forceinline__ void mma_f16_ss(uint32_t d, uint64_t ad, uint64_t bd,
                                           uint32_t idesc, bool acc) {
    uint32_t en = acc ? 1u : 0u;
    asm volatile("{ .reg .pred p; setp.ne.u32 p, %4, 0;"
                 " tcgen05.mma.cta_group::1.kind::f16 [%0], %1, %2, %3, {%5,%5,%5,%5}, p; }"
                 :: "r"(d), "l"(ad), "l"(bd), "r"(idesc), "r"(en), "r"(0u) : "memory");
}
#define TC_LD_X32(r, addr) \
    asm volatile("tcgen05.ld.sync.aligned.32x32b.x32.b32 " \
        "{%0,%1,%2,%3,%4,%5,%6,%7,%8,%9,%10,%11,%12,%13,%14,%15," \
        "%16,%17,%18,%19,%20,%21,%22,%23,%24,%25,%26,%27,%28,%29,%30,%31}, [%32];" \
        : "=r"((r)[0]),"=r"((r)[1]),"=r"((r)[2]),"=r"((r)[3]),"=r"((r)[4]),"=r"((r)[5]), \
          "=r"((r)[6]),"=r"((r)[7]),"=r"((r)[8]),"=r"((r)[9]),"=r"((r)[10]),"=r"((r)[11]), \
          "=r"((r)[12]),"=r"((r)[13]),"=r"((r)[14]),"=r"((r)[15]),"=r"((r)[16]),"=r"((r)[17]), \
          "=r"((r)[18]),"=r"((r)[19]),"=r"((r)[20]),"=r"((r)[21]),"=r"((r)[22]),"=r"((r)[23]), \
          "=r"((r)[24]),"=r"((r)[25]),"=r"((r)[26]),"=r"((r)[27]),"=r"((r)[28]),"=r"((r)[29]), \
          "=r"((r)[30]),"=r"((r)[31]) : "r"(addr))
#define TC_WAIT_LD()  asm volatile("tcgen05.wait::ld.sync.aligned;" ::: "memory")
#define TC_FENCE_AFTER()  asm volatile("tcgen05.fence::after_thread_sync;" ::: "memory")
#define TC_FENCE_BEFORE() asm volatile("tcgen05.fence::before_thread_sync;" ::: "memory")
#endif // HAS_TCGEN05

// ---------------- prep: colscale + cosh/sinh(2 rc b), block per column -------
__global__ void prep_kernel(const float* __restrict__ w, const float* __restrict__ bias,
                            const float* __restrict__ c_ptr, int IN, int OUT) {
    int o = blockIdx.x;
    float s = 0.f;
    for (int i = threadIdx.x; i < IN; i += blockDim.x) {
        float v = w[(size_t)i * OUT + o];
        s = fmaf(v, v, s);
    }
    float tot = block_reduce_sum(s);
    if (threadIdx.x == 0) {
        g_colscale[o] = 1.0f / fmaxf(sqrtf(tot), 1e-15f);
        float rc = sqrtf(c_ptr[0]);
        float d = 2.0f * rc * bias[o];
        g_coshb[o] = coshf(d);
        g_sinhb[o] = sinhf(d);
    }
}

// ---------------- w -> transposed, scaled, bf16 split, SW64 tile-major -------
__global__ void convert_w_kernel(const float* __restrict__ w, int IN, int OUT) {
    __shared__ float t[32][33];
    int n0 = blockIdx.x * 32, k0 = blockIdx.y * 32;
    int tx = threadIdx.x, ty = threadIdx.y;
    t[ty][tx] = w[(size_t)(k0 + ty) * OUT + n0 + tx];   // t[k_local][n_local]
    __syncthreads();
    if (tx < 4) {
        int n = n0 + ty;
        float cs = g_colscale[n];
        uint32_t hi4[4], lo4[4];
        #pragma unroll
        for (int p = 0; p < 4; ++p) {
            float a = t[tx * 8 + p * 2 + 0][ty] * cs;
            float b = t[tx * 8 + p * 2 + 1][ty] * cs;
            __nv_bfloat16 ha = __float2bfloat16(a), hb = __float2bfloat16(b);
            float ra = a - __bfloat162float(ha), rb = b - __bfloat162float(hb);
            hi4[p] = ((uint32_t)__bfloat16_as_ushort(hb) << 16) | __bfloat16_as_ushort(ha);
            lo4[p] = pack_bf16x2(ra, rb);
        }
        // k0 is a multiple of 32 -> kc = blockIdx.y, 16B group = tx
        int nb = n >> 8;
        size_t base = ((size_t)(nb * 32 + blockIdx.y)) * B_TILE
                    + SW64((uint32_t)((n & 255) * 64 + tx * 16));
        *(uint4*)(g_whi_t + base) = make_uint4(hi4[0], hi4[1], hi4[2], hi4[3]);
        *(uint4*)(g_wlo_t + base) = make_uint4(lo4[0], lo4[1], lo4[2], lo4[3]);
    }
}

// ---------------- x -> bf16 hi/lo SW64 tile-major, fused cx2 -----------------
__global__ void convert_x_kernel(const float* __restrict__ x,
                                 const float* __restrict__ c_ptr, int IN) {
    int row = blockIdx.x;
    int t = threadIdx.x;                 // 128 threads, 8 elements each
    if (t < 4) g_ysq_part[(size_t)row * 4 + t] = 0.f;
    const float4* xr = (const float4*)(x + (size_t)row * IN) + t * 2;
    float4 v0 = xr[0], v1 = xr[1];
    float s = v0.x*v0.x + v0.y*v0.y + v0.z*v0.z + v0.w*v0.w
            + v1.x*v1.x + v1.y*v1.y + v1.z*v1.z + v1.w*v1.w;
    float e[8] = {v0.x, v0.y, v0.z, v0.w, v1.x, v1.y, v1.z, v1.w};
    uint32_t hi4[4], lo4[4];
    #pragma unroll
    for (int p = 0; p < 4; ++p) {
        float a = e[p*2], b = e[p*2+1];
        __nv_bfloat16 ha = __float2bfloat16(a), hb = __float2bfloat16(b);
        float ra = a - __bfloat162float(ha), rb = b - __bfloat162float(hb);
        hi4[p] = ((uint32_t)__bfloat16_as_ushort(hb) << 16) | __bfloat16_as_ushort(ha);
        lo4[p] = pack_bf16x2(ra, rb);
    }
    // thread t covers k in [t*8, t*8+8) -> kc = t>>2, 16B group = t&3
    int kc = t >> 2, g = t & 3;
    int rb = row >> 7, r = row & 127;
    size_t base = ((size_t)(rb * 32 + kc)) * A_TILE
                + SW64((uint32_t)(r * 64 + g * 16));
    *(uint4*)(g_xhi_t + base) = make_uint4(hi4[0], hi4[1], hi4[2], hi4[3]);
    *(uint4*)(g_xlo_t + base) = make_uint4(lo4[0], lo4[1], lo4[2], lo4[3]);
    float tot = block_reduce_sum(s);
    if (threadIdx.x == 0) g_cx2[row] = c_ptr[0] * tot;
}

// ---------------- GEMM + fused Poincare epilogue -----------------------------
#define MT 128
#define NT 256
// idesc: F32 out, BF16 a/b, N=256, M=128
#define IDESC ((1u<<4) | (1u<<7) | (1u<<10) | ((NT/8u)<<17) | (8u<<24))

#define OFF_TMEM 0u
#define OFF_MBF  8u                         // full barriers: 8..39 (4)
#define OFF_MBE  40u                        // empty barriers: 40..71 (4)
#define OFF_PAR  1024u                      // 3 * NT floats = 3072 B
#define OFF_T    4096u
#define STAGE    (A_TILE + B_TILE)          // 24 KB
#define NSTAGE   4
#define SMEM_BYTES (OFF_T + NSTAGE * STAGE) // 102400

__global__ __launch_bounds__(128, 2)
void gemm_tc_kernel(const float* __restrict__ X, const float* __restrict__ W,
                    const float* __restrict__ wgp, const float* __restrict__ c_ptr,
                    float* __restrict__ out, int Nrows, int IN, int OUT) {
    extern __shared__ char smem[];
#if HAS_TCGEN05
    const uint32_t sb = smem_u32(smem);
    const int tid = threadIdx.x;
    const int wid = tid >> 5, lane = tid & 31;
    const int brow = blockIdx.y * MT, bcol = blockIdx.x * NT;
    const int nchunk = 96;                   // 3 segments x 32 chunks (KC=32)

    if (wid == 0) { tc_alloc(sb + OFF_TMEM, 256); tc_relinquish(); }
    if (tid == 0) {
        #pragma unroll
        for (int s = 0; s < NSTAGE; ++s) {
            mbar_init(sb + OFF_MBF + 8u * s, 1);
            mbar_init(sb + OFF_MBE + 8u * s, 1);
        }
    }
    float* chb = (float*)(smem + OFF_PAR);
    float* shb = chb + NT;
    float* g2s = shb + NT;
    for (int i = tid; i < NT; i += 128) {
        int o = bcol + i;
        chb[i] = g_coshb[o];
        shb[i] = g_sinhb[o];
        g2s[i] = 2.0f * wgp[o];
    }
    __syncthreads();
    uint32_t tmem;
    asm volatile("ld.shared.b32 %0, [%1];" : "=r"(tmem) : "r"(sb + OFF_TMEM));

    if (tid == 0) {
        auto srcA = [&](int c) -> const uint8_t* {
            int seg = c >> 5, kc = c & 31;
            const uint8_t* p = (seg == 2) ? g_xlo_t : g_xhi_t;
            return p + ((size_t)(blockIdx.y * 32 + kc)) * A_TILE;
        };
        auto srcB = [&](int c) -> const uint8_t* {
            int seg = c >> 5, kc = c & 31;
            const uint8_t* p = (seg == 1) ? g_wlo_t : g_whi_t;
            return p + ((size_t)(blockIdx.x * 32 + kc)) * B_TILE;
        };
        auto load_chunk = [&](int c, int s) {
            uint32_t fb = sb + OFF_MBF + 8u * (uint32_t)s;
            uint32_t base = sb + OFF_T + (uint32_t)s * STAGE;
            mbar_expect_tx(fb, STAGE);
            bulk_g2s(base, srcA(c), A_TILE, fb);
            bulk_g2s(base + A_TILE, srcB(c), B_TILE, fb);
        };
        // prologue: chunks 0..2 into stages 0..2 (distance 3, 4 buffers)
        load_chunk(0, 0);
        load_chunk(1, 1);
        load_chunk(2, 2);

        for (int c = 0; c < nchunk; ++c) {
            const int s = c & 3;
            mbar_wait(sb + OFF_MBF + 8u * (uint32_t)s, (uint32_t)((c >> 2) & 1));
            const uint32_t base = sb + OFF_T + (uint32_t)s * STAGE;
            uint64_t ad = make_desc64(base);
            uint64_t bd = make_desc64(base + A_TILE);
            mma_f16_ss(tmem, ad,     bd,     IDESC, c > 0);
            mma_f16_ss(tmem, ad + 2, bd + 2, IDESC, true);
            tc_commit(sb + OFF_MBE + 8u * (uint32_t)s);
            const int c3 = c + 3;
            if (c3 < nchunk) {
                const int s2 = c3 & 3;           // stage last used by chunk c-1
                if (c >= 1)
                    mbar_wait(sb + OFF_MBE + 8u * (uint32_t)s2,
                              (uint32_t)(((c - 1) >> 2) & 1));
                load_chunk(c3, s2);
            }
        }
        // final commits: stage s last used by chunk 92+s -> commit idx 23 -> parity 1
        mbar_wait(sb + OFF_MBE + 0, 1);
        mbar_wait(sb + OFF_MBE + 8, 1);
        mbar_wait(sb + OFF_MBE + 16, 1);
        mbar_wait(sb + OFF_MBE + 24, 1);
    }
    __syncthreads();
    TC_FENCE_AFTER();

    // ---- epilogue: 4 warps, each owns 32 of this CTA's 128 rows -------------
    const float rc = sqrtf(c_ptr[0]);
    const float invrc = 1.0f / rc;
    const int row = brow + wid * 32 + lane;
    const float cx2 = g_cx2[row];
    const float invd = 1.0f / fmaxf(1.0f - cx2, 1e-15f);
    const float onep = 1.0f + cx2;
    const float two_rc = 2.0f * rc;
    float ysq = 0.f;

    #pragma unroll
    for (int cc = 0; cc < 4; ++cc) {
        const int cb = cc * 64;
        uint32_t d[64];
        TC_LD_X32(d, tmem + cb);
        TC_LD_X32(d + 32, tmem + cb + 32);
        TC_WAIT_LD();
        float* orow = out + (size_t)row * OUT + bcol + cb;
        #pragma unroll
        for (int j = 0; j < 64; j += 4) {
            float yv[4];
            #pragma unroll
            for (int q = 0; q < 4; ++q) {
                int col = cb + j + q;
                float dot = __uint_as_float(d[j + q]);
                float num = fmaf(two_rc * dot, chb[col], -onep * shb[col]);
                float u = num * invd;
                // sinh(g*asinh(u)) = sign(u)*(t^g - t^-g)/2, t = sqrt(u^2+1)+|u|
                float sq = sqrtf(fmaf(u, u, 1.0f));
                float t  = sq + fabsf(u);
                float lt = __logf(t);
                float p  = __expf(g2s[col] * lt);
                float mag = (p - __fdividef(1.0f, p)) * 0.5f * invrc;
                float y = copysignf(mag, u);
                ysq = fmaf(y, y, ysq);
                yv[q] = y;
            }
            *(float4*)(orow + j) = make_float4(yv[0], yv[1], yv[2], yv[3]);
        }
    }
    g_ysq_part[(size_t)row * 4 + blockIdx.x] = ysq;

    TC_FENCE_BEFORE();
    __syncthreads();
    if (wid == 0) tc_dealloc(tmem, 256);

#else  // ------------- SIMT fallback (non-'a' PTX stage; never runs on GB300) -
    float (*As)[128] = (float(*)[128])(smem);
    float (*Bs)[128] = (float(*)[128])(smem + 16 * 128 * 4);

    const int tid = threadIdx.x;               // 128 threads
    const int brow = blockIdx.y * MT;
    const float cval = c_ptr[0];
    const float rc = sqrtf(cval);
    const float invrc = 1.0f / rc;
    const int tx = tid & 15, ty = tid >> 4;     // 16 col-groups x 8 row-groups

    for (int nh = 0; nh < 2; ++nh) {
        const int bcol = blockIdx.x * NT + nh * 128;
        float acc[16][8];
        #pragma unroll
        for (int i = 0; i < 16; ++i)
            #pragma unroll
            for (int j = 0; j < 8; ++j) acc[i][j] = 0.f;

        for (int kt = 0; kt < IN; kt += 16) {
            #pragma unroll
            for (int l = 0; l < 4; ++l) {
                int idx = tid + l * 128;
                int r = idx >> 2, c4 = (idx & 3) << 2;
                float4 v = *(const float4*)(X + (size_t)(brow + r) * IN + kt + c4);
                As[c4 + 0][r] = v.x; As[c4 + 1][r] = v.y;
                As[c4 + 2][r] = v.z; As[c4 + 3][r] = v.w;
            }
            #pragma unroll
            for (int l = 0; l < 4; ++l) {
                int idx = tid + l * 128;
                int r = idx >> 5, c4 = (idx & 31) << 2;
                *(float4*)(&Bs[r][c4]) =
                    *(const float4*)(W + (size_t)(kt + r) * OUT + bcol + c4);
            }
            __syncthreads();
            #pragma unroll
            for (int k = 0; k < 16; ++k) {
                float a[16], b[8];
                #pragma unroll
                for (int q = 0; q < 16; ++q) a[q] = As[k][ty * 16 + q];
                #pragma unroll
                for (int q = 0; q < 8; ++q) b[q] = Bs[k][tx * 8 + q];
                #pragma unroll
                for (int i = 0; i < 16; ++i)
                    #pragma unroll
                    for (int j = 0; j < 8; ++j)
                        acc[i][j] = fmaf(a[i], b[j], acc[i][j]);
            }
            __syncthreads();
        }
        #pragma unroll
        for (int i = 0; i < 16; ++i) {
            int n = brow + ty * 16 + i;
            float cx2 = g_cx2[n];
            float invd = 1.0f / fmaxf(1.0f - cx2, 1e-15f);
            float onep = 1.0f + cx2;
            float y[8];
            float ysq = 0.f;
            #pragma unroll
            for (int j = 0; j < 8; ++j) {
                int o = bcol + tx * 8 + j;
                float num = 2.0f * rc * acc[i][j] * g_colscale[o] * g_coshb[o]
                            - onep * g_sinhb[o];
                float a = 2.0f * wgp[o] * asinhf(num * invd);
                y[j] = sinhf(a) * invrc;
                ysq = fmaf(y[j], y[j], ysq);
            }
            atomicAdd(&g_ysq_part[(size_t)n * 4 + blockIdx.x], ysq);
            float* orow = out + (size_t)n * OUT + bcol + tx * 8;
            *(float4*)(orow)     = make_float4(y[0], y[1], y[2], y[3]);
            *(float4*)(orow + 4) = make_float4(y[4], y[5], y[6], y[7]);
        }
        __syncthreads();
    }
#endif
}

// ---------------- rescale: gyro-half map + ball projection -------------------
__global__ void rescale_kernel(float* __restrict__ out,
                               const float* __restrict__ c_ptr, int OUT) {
    int row = blockIdx.x;
    float tot = g_ysq_part[(size_t)row * 4 + 0] + g_ysq_part[(size_t)row * 4 + 1]
              + g_ysq_part[(size_t)row * 4 + 2] + g_ysq_part[(size_t)row * 4 + 3];
    float c = c_ptr[0];
    float denom = 1.0f + sqrtf(1.0f + c * tot);
    float scale = 1.0f / denom;
    float norm = fmaxf(sqrtf(tot) * scale, 1e-15f);
    float kk = -c;
    float maxnorm = (1.0f - 0.004f) * rsqrtf(fmaxf(fabsf(kk), 1e-15f));
    if (!(kk < 0.f)) maxnorm = 1e15f;
    if (norm > maxnorm) scale *= maxnorm / norm;

    float4* yr = (float4*)(out + (size_t)row * OUT);
    int n4 = OUT >> 2;
    for (int i = threadIdx.x; i < n4; i += blockDim.x) {
        float4 v = yr[i];
        v.x *= scale; v.y *= scale; v.z *= scale; v.w *= scale;
        yr[i] = v;
    }
}

// ---------------------------------------------------------------------------
extern "C" void kernel_launch(void* const* d_in, const int* in_sizes, int n_in,
                              void* d_out, int out_size) {
    const float* x    = (const float*)d_in[0];
    const float* w    = (const float*)d_in[1];
    const float* wg   = (const float*)d_in[2];
    const float* bias = (const float*)d_in[3];
    const float* c    = (const float*)d_in[4];
    float* out = (float*)d_out;

    int OUT = in_sizes[2];
    int IN  = in_sizes[1] / OUT;
    int N   = in_sizes[0] / IN;

    static int smem_set = 0;
    if (!smem_set) {
        cudaFuncSetAttribute(gemm_tc_kernel, cudaFuncAttributeMaxDynamicSharedMemorySize,
                             SMEM_BYTES);
        smem_set = 1;
    }

    prep_kernel<<<OUT, 256>>>(w, bias, c, IN, OUT);
    convert_w_kernel<<<dim3(OUT / 32, IN / 32), dim3(32, 32)>>>(w, IN, OUT);
    convert_x_kernel<<<N, 128>>>(x, c, IN);
    dim3 grid(OUT / NT, N / MT);              // (4, 256)
    gemm_tc_kernel<<<grid, 128, SMEM_BYTES>>>(x, w, wg, c, out, N, IN, OUT);
    rescale_kernel<<<N, 256>>>(out, c, OUT);
}

// round 13
// speedup vs baseline: 1.5692x; 1.3707x over previous
#include <cuda_runtime.h>
#include <cuda_bf16.h>
#include <math.h>
#include <stdint.h>

// ---------------------------------------------------------------------------
// PoincareLinear via tcgen05 bf16 split GEMM (sm_103a) + SIMT fallback body.
//   dot = x_hi@w_hi + x_hi@w_lo + x_lo@w_hi   (K_eff = 3*1024)
//   R13: 4 CTAs/SM. Per-CTA tile 128x128, KC=32 (SW64, 64B rows),
//   3 stages x 16KB (52KB smem/CTA), distance 2, TMEM 128 cols/CTA.
//   Model: per-CTA async ingestion ~15 B/cyc; rates add across CTAs/SM.
// ---------------------------------------------------------------------------

#if defined(__CUDA_ARCH_FEAT_SM103_ALL) || defined(__CUDA_ARCH_FEAT_SM100_ALL) || \
    defined(__CUDA_ARCH_SPECIFIC__) || defined(__CUDA_ARCH_FAMILY_SPECIFIC__)
#define HAS_TCGEN05 1
#else
#define HAS_TCGEN05 0
#endif

#define N_MAX   32768
#define IN_MAX  1024
#define OUT_MAX 1024
#define A_TILE  8192u                // 128 rows x 64 B (KC=32)
#define B_TILE  8192u                // 128 rows x 64 B

// tile-major, pre-SW64-swizzled blobs:
//   X: tile(rb,kc) at (rb*32+kc)*A_TILE,  rb = row>>7,  kc = k>>5
//   W: tile(nb,kc) at (nb*32+kc)*B_TILE,  nb = n>>7,    kc = k>>5
__device__ uint8_t g_xhi_t[(size_t)N_MAX * IN_MAX * 2];
__device__ uint8_t g_xlo_t[(size_t)N_MAX * IN_MAX * 2];
__device__ uint8_t g_whi_t[(size_t)OUT_MAX * IN_MAX * 2];
__device__ uint8_t g_wlo_t[(size_t)OUT_MAX * IN_MAX * 2];
__device__ float g_colscale[OUT_MAX];
__device__ float g_coshb[OUT_MAX];
__device__ float g_sinhb[OUT_MAX];
__device__ float g_cx2[N_MAX];
__device__ float g_ysq_part[(size_t)N_MAX * 8];   // 8 col-CTAs now

// SW64 descriptor: layout=4, version=1, SBO=32, LBO=1.
constexpr uint64_t kSmemDescBaseSW64 =
    (uint64_t(4) << 61) | (uint64_t(1) << 46) | (uint64_t(32) << 32) | (uint64_t(1) << 16);

// ---------------- generic helpers -------------------------------------------
__device__ __forceinline__ uint32_t smem_u32(const void* p) {
    uint32_t a;
    asm("{ .reg .u64 t; cvta.to.shared.u64 t, %1; cvt.u32.u64 %0, t; }"
        : "=r"(a) : "l"(p));
    return a;
}
#define SW64(off) ((off) ^ (((off) >> 3) & 0x30))

__device__ __forceinline__ float block_reduce_sum(float v) {
    __shared__ float red[32];
    int lane = threadIdx.x & 31, wid = threadIdx.x >> 5;
    #pragma unroll
    for (int o = 16; o > 0; o >>= 1) v += __shfl_down_sync(0xffffffff, v, o);
    if (lane == 0) red[wid] = v;
    __syncthreads();
    int nw = (blockDim.x + 31) >> 5;
    v = (threadIdx.x < nw) ? red[threadIdx.x] : 0.f;
    if (wid == 0)
        #pragma unroll
        for (int o = 16; o > 0; o >>= 1) v += __shfl_down_sync(0xffffffff, v, o);
    return v;
}

__device__ __forceinline__ uint32_t pack_bf16x2(float a, float b) {
    __nv_bfloat16 ha = __float2bfloat16(a), hb = __float2bfloat16(b);
    return ((uint32_t)__bfloat16_as_ushort(hb) << 16) | __bfloat16_as_ushort(ha);
}

#if HAS_TCGEN05
// ---------------- tcgen05 / mbarrier / bulk-copy wrappers --------------------
__device__ __forceinline__ uint64_t make_desc64(uint32_t addr) {
    return kSmemDescBaseSW64 | ((uint64_t)(addr >> 4) & 0x3FFF);
}
__device__ __forceinline__ void mbar_init(uint32_t a, uint32_t cnt) {
    asm volatile("mbarrier.init.shared.b64 [%0], %1;" :: "r"(a), "r"(cnt) : "memory");
}
__device__ __forceinline__ void mbar_expect_tx(uint32_t a, uint32_t bytes) {
    asm volatile("mbarrier.arrive.expect_tx.shared.b64 _, [%0], %1;"
                 :: "r"(a), "r"(bytes) : "memory");
}
__device__ __forceinline__ void mbar_wait(uint32_t a, uint32_t parity) {
    uint32_t done;
    asm volatile("{ .reg .pred p; mbarrier.try_wait.parity.acquire.cta.shared::cta.b64 p, [%1], %2;"
                 " selp.b32 %0,1,0,p; }" : "=r"(done) : "r"(a), "r"(parity) : "memory");
    if (!done) {
        asm volatile("{ .reg .pred P1; WL%=:"
                     " mbarrier.try_wait.parity.acquire.cta.shared::cta.b64 P1, [%0], %1, 0x989680;"
                     " @P1 bra.uni WD%=; bra.uni WL%=; WD%=: }"
                     :: "r"(a), "r"(parity) : "memory");
    }
}
__device__ __forceinline__ void bulk_g2s(uint32_t dst, const void* src, uint32_t bytes,
                                         uint32_t mbar) {
    asm volatile("cp.async.bulk.shared::cta.global.mbarrier::complete_tx::bytes"
                 " [%0], [%1], %2, [%3];"
                 :: "r"(dst), "l"(src), "r"(bytes), "r"(mbar) : "memory");
}
__device__ __forceinline__ void tc_alloc(uint32_t smem_dst, uint32_t ncols) {
    asm volatile("tcgen05.alloc.cta_group::1.sync.aligned.shared::cta.b32 [%0], %1;"
                 :: "r"(smem_dst), "r"(ncols) : "memory");
}
__device__ __forceinline__ void tc_dealloc(uint32_t tmem, uint32_t ncols) {
    asm volatile("tcgen05.dealloc.cta_group::1.sync.aligned.b32 %0, %1;" :: "r"(tmem), "r"(ncols));
}
__device__ __forceinline__ void tc_relinquish() {
    asm volatile("tcgen05.relinquish_alloc_permit.cta_group::1.sync.aligned;");
}
__device__ __forceinline__ void tc_commit(uint32_t mbar) {
    asm volatile("tcgen05.commit.cta_group::1.mbarrier::arrive::one.shared::cluster.b64 [%0];"
                 :: "r"(mbar) : "memory");
}
__device__ __forceinline__ void mma_f16_ss(uint32_t d, uint64_t ad, uint64_t bd,
                                           uint32_t idesc, bool acc) {
    uint32_t en = acc ? 1u : 0u;
    asm volatile("{ .reg .pred p; setp.ne.u32 p, %4, 0;"
                 " tcgen05.mma.cta_group::1.kind::f16 [%0], %1, %2, %3, {%5,%5,%5,%5}, p; }"
                 :: "r"(d), "l"(ad), "l"(bd), "r"(idesc), "r"(en), "r"(0u) : "memory");
}
#define TC_LD_X32(r, addr) \
    asm volatile("tcgen05.ld.sync.aligned.32x32b.x32.b32 " \
        "{%0,%1,%2,%3,%4,%5,%6,%7,%8,%9,%10,%11,%12,%13,%14,%15," \
        "%16,%17,%18,%19,%20,%21,%22,%23,%24,%25,%26,%27,%28,%29,%30,%31}, [%32];" \
        : "=r"((r)[0]),"=r"((r)[1]),"=r"((r)[2]),"=r"((r)[3]),"=r"((r)[4]),"=r"((r)[5]), \
          "=r"((r)[6]),"=r"((r)[7]),"=r"((r)[8]),"=r"((r)[9]),"=r"((r)[10]),"=r"((r)[11]), \
          "=r"((r)[12]),"=r"((r)[13]),"=r"((r)[14]),"=r"((r)[15]),"=r"((r)[16]),"=r"((r)[17]), \
          "=r"((r)[18]),"=r"((r)[19]),"=r"((r)[20]),"=r"((r)[21]),"=r"((r)[22]),"=r"((r)[23]), \
          "=r"((r)[24]),"=r"((r)[25]),"=r"((r)[26]),"=r"((r)[27]),"=r"((r)[28]),"=r"((r)[29]), \
          "=r"((r)[30]),"=r"((r)[31]) : "r"(addr))
#define TC_WAIT_LD()  asm volatile("tcgen05.wait::ld.sync.aligned;" ::: "memory")
#define TC_FENCE_AFTER()  asm volatile("tcgen05.fence::after_thread_sync;" ::: "memory")
#define TC_FENCE_BEFORE() asm volatile("tcgen05.fence::before_thread_sync;" ::: "memory")
#endif // HAS_TCGEN05

// ---------------- prep: colscale + cosh/sinh(2 rc b), block per column -------
__global__ void prep_kernel(const float* __restrict__ w, const float* __restrict__ bias,
                            const float* __restrict__ c_ptr, int IN, int OUT) {
    int o = blockIdx.x;
    float s = 0.f;
    for (int i = threadIdx.x; i < IN; i += blockDim.x) {
        float v = w[(size_t)i * OUT + o];
        s = fmaf(v, v, s);
    }
    float tot = block_reduce_sum(s);
    if (threadIdx.x == 0) {
        g_colscale[o] = 1.0f / fmaxf(sqrtf(tot), 1e-15f);
        float rc = sqrtf(c_ptr[0]);
        float d = 2.0f * rc * bias[o];
        g_coshb[o] = coshf(d);
        g_sinhb[o] = sinhf(d);
    }
}

// ---------------- w -> transposed, scaled, bf16 split, SW64 tile-major -------
__global__ void convert_w_kernel(const float* __restrict__ w, int IN, int OUT) {
    __shared__ float t[32][33];
    int n0 = blockIdx.x * 32, k0 = blockIdx.y * 32;
    int tx = threadIdx.x, ty = threadIdx.y;
    t[ty][tx] = w[(size_t)(k0 + ty) * OUT + n0 + tx];   // t[k_local][n_local]
    __syncthreads();
    if (tx < 4) {
        int n = n0 + ty;
        float cs = g_colscale[n];
        uint32_t hi4[4], lo4[4];
        #pragma unroll
        for (int p = 0; p < 4; ++p) {
            float a = t[tx * 8 + p * 2 + 0][ty] * cs;
            float b = t[tx * 8 + p * 2 + 1][ty] * cs;
            __nv_bfloat16 ha = __float2bfloat16(a), hb = __float2bfloat16(b);
            float ra = a - __bfloat162float(ha), rb = b - __bfloat162float(hb);
            hi4[p] = ((uint32_t)__bfloat16_as_ushort(hb) << 16) | __bfloat16_as_ushort(ha);
            lo4[p] = pack_bf16x2(ra, rb);
        }
        // nb = n>>7 (NT=128), kc = blockIdx.y, 16B group = tx
        int nb = n >> 7;
        size_t base = ((size_t)(nb * 32 + blockIdx.y)) * B_TILE
                    + SW64((uint32_t)((n & 127) * 64 + tx * 16));
        *(uint4*)(g_whi_t + base) = make_uint4(hi4[0], hi4[1], hi4[2], hi4[3]);
        *(uint4*)(g_wlo_t + base) = make_uint4(lo4[0], lo4[1], lo4[2], lo4[3]);
    }
}

// ---------------- x -> bf16 hi/lo SW64 tile-major, fused cx2 -----------------
__global__ void convert_x_kernel(const float* __restrict__ x,
                                 const float* __restrict__ c_ptr, int IN) {
    int row = blockIdx.x;
    int t = threadIdx.x;                 // 128 threads, 8 elements each
    if (t < 8) g_ysq_part[(size_t)row * 8 + t] = 0.f;
    const float4* xr = (const float4*)(x + (size_t)row * IN) + t * 2;
    float4 v0 = xr[0], v1 = xr[1];
    float s = v0.x*v0.x + v0.y*v0.y + v0.z*v0.z + v0.w*v0.w
            + v1.x*v1.x + v1.y*v1.y + v1.z*v1.z + v1.w*v1.w;
    float e[8] = {v0.x, v0.y, v0.z, v0.w, v1.x, v1.y, v1.z, v1.w};
    uint32_t hi4[4], lo4[4];
    #pragma unroll
    for (int p = 0; p < 4; ++p) {
        float a = e[p*2], b = e[p*2+1];
        __nv_bfloat16 ha = __float2bfloat16(a), hb = __float2bfloat16(b);
        float ra = a - __bfloat162float(ha), rb = b - __bfloat162float(hb);
        hi4[p] = ((uint32_t)__bfloat16_as_ushort(hb) << 16) | __bfloat16_as_ushort(ha);
        lo4[p] = pack_bf16x2(ra, rb);
    }
    // thread t covers k in [t*8, t*8+8) -> kc = t>>2, 16B group = t&3
    int kc = t >> 2, g = t & 3;
    int rb = row >> 7, r = row & 127;
    size_t base = ((size_t)(rb * 32 + kc)) * A_TILE
                + SW64((uint32_t)(r * 64 + g * 16));
    *(uint4*)(g_xhi_t + base) = make_uint4(hi4[0], hi4[1], hi4[2], hi4[3]);
    *(uint4*)(g_xlo_t + base) = make_uint4(lo4[0], lo4[1], lo4[2], lo4[3]);
    float tot = block_reduce_sum(s);
    if (threadIdx.x == 0) g_cx2[row] = c_ptr[0] * tot;
}

// ---------------- GEMM + fused Poincare epilogue -----------------------------
#define MT 128
#define NT 128
// idesc: F32 out, BF16 a/b, N=128, M=128
#define IDESC ((1u<<4) | (1u<<7) | (1u<<10) | ((NT/8u)<<17) | (8u<<24))

#define OFF_TMEM 0u
#define OFF_MBF  8u                         // full barriers: 8,16,24
#define OFF_MBE  32u                        // empty barriers: 32,40,48
#define OFF_PAR  1024u                      // 3 * NT floats = 1536 B
#define OFF_T    4096u
#define STAGE    (A_TILE + B_TILE)          // 16 KB
#define NSTAGE   3
#define SMEM_BYTES (OFF_T + NSTAGE * STAGE) // 53248

__global__ __launch_bounds__(128, 4)
void gemm_tc_kernel(const float* __restrict__ X, const float* __restrict__ W,
                    const float* __restrict__ wgp, const float* __restrict__ c_ptr,
                    float* __restrict__ out, int Nrows, int IN, int OUT) {
    extern __shared__ char smem[];
#if HAS_TCGEN05
    const uint32_t sb = smem_u32(smem);
    const int tid = threadIdx.x;
    const int wid = tid >> 5, lane = tid & 31;
    const int brow = blockIdx.y * MT, bcol = blockIdx.x * NT;
    const int nchunk = 96;                   // 3 segments x 32 chunks (KC=32)

    if (wid == 0) { tc_alloc(sb + OFF_TMEM, 128); tc_relinquish(); }
    if (tid == 0) {
        #pragma unroll
        for (int s = 0; s < NSTAGE; ++s) {
            mbar_init(sb + OFF_MBF + 8u * s, 1);
            mbar_init(sb + OFF_MBE + 8u * s, 1);
        }
    }
    float* chb = (float*)(smem + OFF_PAR);
    float* shb = chb + NT;
    float* g2s = shb + NT;
    if (tid < NT) {
        int o = bcol + tid;
        chb[tid] = g_coshb[o];
        shb[tid] = g_sinhb[o];
        g2s[tid] = 2.0f * wgp[o];
    }
    __syncthreads();
    uint32_t tmem;
    asm volatile("ld.shared.b32 %0, [%1];" : "=r"(tmem) : "r"(sb + OFF_TMEM));

    if (tid == 0) {
        auto srcA = [&](int c) -> const uint8_t* {
            int seg = c >> 5, kc = c & 31;
            const uint8_t* p = (seg == 2) ? g_xlo_t : g_xhi_t;
            return p + ((size_t)(blockIdx.y * 32 + kc)) * A_TILE;
        };
        auto srcB = [&](int c) -> const uint8_t* {
            int seg = c >> 5, kc = c & 31;
            const uint8_t* p = (seg == 1) ? g_wlo_t : g_whi_t;
            return p + ((size_t)(blockIdx.x * 32 + kc)) * B_TILE;
        };
        auto load_chunk = [&](int c, int s) {
            uint32_t fb = sb + OFF_MBF + 8u * (uint32_t)s;
            uint32_t base = sb + OFF_T + (uint32_t)s * STAGE;
            mbar_expect_tx(fb, STAGE);
            bulk_g2s(base, srcA(c), A_TILE, fb);
            bulk_g2s(base + A_TILE, srcB(c), B_TILE, fb);
        };
        load_chunk(0, 0);
        load_chunk(1, 1);

        for (int c = 0; c < nchunk; ++c) {
            const int s = c % 3;
            mbar_wait(sb + OFF_MBF + 8u * (uint32_t)s, (uint32_t)((c / 3) & 1));
            const uint32_t base = sb + OFF_T + (uint32_t)s * STAGE;
            uint64_t ad = make_desc64(base);
            uint64_t bd = make_desc64(base + A_TILE);
            mma_f16_ss(tmem, ad,     bd,     IDESC, c > 0);
            mma_f16_ss(tmem, ad + 2, bd + 2, IDESC, true);
            tc_commit(sb + OFF_MBE + 8u * (uint32_t)s);
            const int c2 = c + 2;
            if (c2 < nchunk) {
                const int s2 = c2 % 3;           // stage last used by chunk c-1
                if (c >= 1)
                    mbar_wait(sb + OFF_MBE + 8u * (uint32_t)s2,
                              (uint32_t)(((c - 1) / 3) & 1));
                load_chunk(c2, s2);
            }
        }
        // final commits: 32 per stage -> last commit index 31 -> parity 1
        mbar_wait(sb + OFF_MBE + 0, 1);
        mbar_wait(sb + OFF_MBE + 8, 1);
        mbar_wait(sb + OFF_MBE + 16, 1);
    }
    __syncthreads();
    TC_FENCE_AFTER();

    // ---- epilogue: 4 warps, each owns 32 of this CTA's 128 rows, 128 cols ---
    const float rc = sqrtf(c_ptr[0]);
    const float invrc = 1.0f / rc;
    const int row = brow + wid * 32 + lane;
    const float cx2 = g_cx2[row];
    const float invd = 1.0f / fmaxf(1.0f - cx2, 1e-15f);
    const float onep = 1.0f + cx2;
    const float two_rc = 2.0f * rc;
    float ysq = 0.f;

    #pragma unroll
    for (int cc = 0; cc < 2; ++cc) {
        const int cb = cc * 64;
        uint32_t d[64];
        TC_LD_X32(d, tmem + cb);
        TC_LD_X32(d + 32, tmem + cb + 32);
        TC_WAIT_LD();
        float* orow = out + (size_t)row * OUT + bcol + cb;
        #pragma unroll
        for (int j = 0; j < 64; j += 4) {
            float yv[4];
            #pragma unroll
            for (int q = 0; q < 4; ++q) {
                int col = cb + j + q;
                float dot = __uint_as_float(d[j + q]);
                float num = fmaf(two_rc * dot, chb[col], -onep * shb[col]);
                float u = num * invd;
                // sinh(g*asinh(u)) = sign(u)*(t^g - t^-g)/2, t = sqrt(u^2+1)+|u|
                float sq = sqrtf(fmaf(u, u, 1.0f));
                float t  = sq + fabsf(u);
                float lt = __logf(t);
                float p  = __expf(g2s[col] * lt);
                float mag = (p - __fdividef(1.0f, p)) * 0.5f * invrc;
                float y = copysignf(mag, u);
                ysq = fmaf(y, y, ysq);
                yv[q] = y;
            }
            *(float4*)(orow + j) = make_float4(yv[0], yv[1], yv[2], yv[3]);
        }
    }
    g_ysq_part[(size_t)row * 8 + blockIdx.x] = ysq;

    TC_FENCE_BEFORE();
    __syncthreads();
    if (wid == 0) tc_dealloc(tmem, 128);

#else  // ------------- SIMT fallback (non-'a' PTX stage; never runs on GB300) -
    float (*As)[128] = (float(*)[128])(smem);
    float (*Bs)[128] = (float(*)[128])(smem + 16 * 128 * 4);

    const int tid = threadIdx.x;               // 128 threads
    const int brow = blockIdx.y * MT;
    const int bcol = blockIdx.x * NT;
    const float cval = c_ptr[0];
    const float rc = sqrtf(cval);
    const float invrc = 1.0f / rc;
    const int tx = tid & 15, ty = tid >> 4;     // 16 col-groups x 8 row-groups

    float acc[16][8];
    #pragma unroll
    for (int i = 0; i < 16; ++i)
        #pragma unroll
        for (int j = 0; j < 8; ++j) acc[i][j] = 0.f;

    for (int kt = 0; kt < IN; kt += 16) {
        #pragma unroll
        for (int l = 0; l < 4; ++l) {
            int idx = tid + l * 128;
            int r = idx >> 2, c4 = (idx & 3) << 2;
            float4 v = *(const float4*)(X + (size_t)(brow + r) * IN + kt + c4);
            As[c4 + 0][r] = v.x; As[c4 + 1][r] = v.y;
            As[c4 + 2][r] = v.z; As[c4 + 3][r] = v.w;
        }
        #pragma unroll
        for (int l = 0; l < 4; ++l) {
            int idx = tid + l * 128;
            int r = idx >> 5, c4 = (idx & 31) << 2;
            if (c4 < 128)
                *(float4*)(&Bs[r][c4]) =
                    *(const float4*)(W + (size_t)(kt + r) * OUT + bcol + c4);
        }
        __syncthreads();
        #pragma unroll
        for (int k = 0; k < 16; ++k) {
            float a[16], b[8];
            #pragma unroll
            for (int q = 0; q < 16; ++q) a[q] = As[k][ty * 16 + q];
            #pragma unroll
            for (int q = 0; q < 8; ++q) b[q] = Bs[k][tx * 8 + q];
            #pragma unroll
            for (int i = 0; i < 16; ++i)
                #pragma unroll
                for (int j = 0; j < 8; ++j)
                    acc[i][j] = fmaf(a[i], b[j], acc[i][j]);
        }
        __syncthreads();
    }
    #pragma unroll
    for (int i = 0; i < 16; ++i) {
        int n = brow + ty * 16 + i;
        float cx2 = g_cx2[n];
        float invd = 1.0f / fmaxf(1.0f - cx2, 1e-15f);
        float onep = 1.0f + cx2;
        float y[8];
        float ysq = 0.f;
        #pragma unroll
        for (int j = 0; j < 8; ++j) {
            int o = bcol + tx * 8 + j;
            float num = 2.0f * rc * acc[i][j] * g_colscale[o] * g_coshb[o]
                        - onep * g_sinhb[o];
            float a = 2.0f * wgp[o] * asinhf(num * invd);
            y[j] = sinhf(a) * invrc;
            ysq = fmaf(y[j], y[j], ysq);
        }
        atomicAdd(&g_ysq_part[(size_t)n * 8 + blockIdx.x], ysq);
        float* orow = out + (size_t)n * OUT + bcol + tx * 8;
        *(float4*)(orow)     = make_float4(y[0], y[1], y[2], y[3]);
        *(float4*)(orow + 4) = make_float4(y[4], y[5], y[6], y[7]);
    }
#endif
}

// ---------------- rescale: gyro-half map + ball projection -------------------
__global__ void rescale_kernel(float* __restrict__ out,
                               const float* __restrict__ c_ptr, int OUT) {
    int row = blockIdx.x;
    float tot = 0.f;
    #pragma unroll
    for (int i = 0; i < 8; ++i) tot += g_ysq_part[(size_t)row * 8 + i];
    float c = c_ptr[0];
    float denom = 1.0f + sqrtf(1.0f + c * tot);
    float scale = 1.0f / denom;
    float norm = fmaxf(sqrtf(tot) * scale, 1e-15f);
    float kk = -c;
    float maxnorm = (1.0f - 0.004f) * rsqrtf(fmaxf(fabsf(kk), 1e-15f));
    if (!(kk < 0.f)) maxnorm = 1e15f;
    if (norm > maxnorm) scale *= maxnorm / norm;

    float4* yr = (float4*)(out + (size_t)row * OUT);
    int n4 = OUT >> 2;
    for (int i = threadIdx.x; i < n4; i += blockDim.x) {
        float4 v = yr[i];
        v.x *= scale; v.y *= scale; v.z *= scale; v.w *= scale;
        yr[i] = v;
    }
}

// ---------------------------------------------------------------------------
extern "C" void kernel_launch(void* const* d_in, const int* in_sizes, int n_in,
                              void* d_out, int out_size) {
    const float* x    = (const float*)d_in[0];
    const float* w    = (const float*)d_in[1];
    const float* wg   = (const float*)d_in[2];
    const float* bias = (const float*)d_in[3];
    const float* c    = (const float*)d_in[4];
    float* out = (float*)d_out;

    int OUT = in_sizes[2];
    int IN  = in_sizes[1] / OUT;
    int N   = in_sizes[0] / IN;

    static int smem_set = 0;
    if (!smem_set) {
        cudaFuncSetAttribute(gemm_tc_kernel, cudaFuncAttributeMaxDynamicSharedMemorySize,
                             SMEM_BYTES);
        smem_set = 1;
    }

    prep_kernel<<<OUT, 256>>>(w, bias, c, IN, OUT);
    convert_w_kernel<<<dim3(OUT / 32, IN / 32), dim3(32, 32)>>>(w, IN, OUT);
    convert_x_kernel<<<N, 128>>>(x, c, IN);
    dim3 grid(OUT / NT, N / MT);              // (8, 256) = 2048 CTAs
    gemm_tc_kernel<<<grid, 128, SMEM_BYTES>>>(x, w, wg, c, out, N, IN, OUT);
    rescale_kernel<<<N, 256>>>(out, c, OUT);
}

// round 14
// speedup vs baseline: 1.7131x; 1.0917x over previous
#include <cuda_runtime.h>
#include <cuda_bf16.h>
#include <math.h>
#include <stdint.h>

// ---------------------------------------------------------------------------
// PoincareLinear via tcgen05 bf16 split GEMM (sm_103a) + SIMT fallback body.
//   dot = x_hi@w_hi + x_hi@w_lo + x_lo@w_hi   (K_eff = 3*1024)
//   R14: 4 CTAs/SM, 128x128 tile, KC=32 (SW64), 3 stages x 16KB.
//   Warp-specialized mainloop: producer warp issues bulk loads (distance 3),
//   consumer warp issues MMAs + commits. Sync purely via full/empty mbarriers.
// ---------------------------------------------------------------------------

#if defined(__CUDA_ARCH_FEAT_SM103_ALL) || defined(__CUDA_ARCH_FEAT_SM100_ALL) || \
    defined(__CUDA_ARCH_SPECIFIC__) || defined(__CUDA_ARCH_FAMILY_SPECIFIC__)
#define HAS_TCGEN05 1
#else
#define HAS_TCGEN05 0
#endif

#define N_MAX   32768
#define IN_MAX  1024
#define OUT_MAX 1024
#define A_TILE  8192u                // 128 rows x 64 B (KC=32)
#define B_TILE  8192u                // 128 rows x 64 B

// tile-major, pre-SW64-swizzled blobs:
//   X: tile(rb,kc) at (rb*32+kc)*A_TILE,  rb = row>>7,  kc = k>>5
//   W: tile(nb,kc) at (nb*32+kc)*B_TILE,  nb = n>>7,    kc = k>>5
__device__ uint8_t g_xhi_t[(size_t)N_MAX * IN_MAX * 2];
__device__ uint8_t g_xlo_t[(size_t)N_MAX * IN_MAX * 2];
__device__ uint8_t g_whi_t[(size_t)OUT_MAX * IN_MAX * 2];
__device__ uint8_t g_wlo_t[(size_t)OUT_MAX * IN_MAX * 2];
__device__ float g_colscale[OUT_MAX];
__device__ float g_coshb[OUT_MAX];
__device__ float g_sinhb[OUT_MAX];
__device__ float g_cx2[N_MAX];
__device__ float g_ysq_part[(size_t)N_MAX * 8];

// SW64 descriptor: layout=4, version=1, SBO=32, LBO=1.
constexpr uint64_t kSmemDescBaseSW64 =
    (uint64_t(4) << 61) | (uint64_t(1) << 46) | (uint64_t(32) << 32) | (uint64_t(1) << 16);

// ---------------- generic helpers -------------------------------------------
__device__ __forceinline__ uint32_t smem_u32(const void* p) {
    uint32_t a;
    asm("{ .reg .u64 t; cvta.to.shared.u64 t, %1; cvt.u32.u64 %0, t; }"
        : "=r"(a) : "l"(p));
    return a;
}
#define SW64(off) ((off) ^ (((off) >> 3) & 0x30))

__device__ __forceinline__ float block_reduce_sum(float v) {
    __shared__ float red[32];
    int lane = threadIdx.x & 31, wid = threadIdx.x >> 5;
    #pragma unroll
    for (int o = 16; o > 0; o >>= 1) v += __shfl_down_sync(0xffffffff, v, o);
    if (lane == 0) red[wid] = v;
    __syncthreads();
    int nw = (blockDim.x + 31) >> 5;
    v = (threadIdx.x < nw) ? red[threadIdx.x] : 0.f;
    if (wid == 0)
        #pragma unroll
        for (int o = 16; o > 0; o >>= 1) v += __shfl_down_sync(0xffffffff, v, o);
    return v;
}

__device__ __forceinline__ uint32_t pack_bf16x2(float a, float b) {
    __nv_bfloat16 ha = __float2bfloat16(a), hb = __float2bfloat16(b);
    return ((uint32_t)__bfloat16_as_ushort(hb) << 16) | __bfloat16_as_ushort(ha);
}

#if HAS_TCGEN05
// ---------------- tcgen05 / mbarrier / bulk-copy wrappers --------------------
__device__ __forceinline__ uint64_t make_desc64(uint32_t addr) {
    return kSmemDescBaseSW64 | ((uint64_t)(addr >> 4) & 0x3FFF);
}
__device__ __forceinline__ void mbar_init(uint32_t a, uint32_t cnt) {
    asm volatile("mbarrier.init.shared.b64 [%0], %1;" :: "r"(a), "r"(cnt) : "memory");
}
__device__ __forceinline__ void mbar_expect_tx(uint32_t a, uint32_t bytes) {
    asm volatile("mbarrier.arrive.expect_tx.shared.b64 _, [%0], %1;"
                 :: "r"(a), "r"(bytes) : "memory");
}
__device__ __forceinline__ void mbar_wait(uint32_t a, uint32_t parity) {
    uint32_t done;
    asm volatile("{ .reg .pred p; mbarrier.try_wait.parity.acquire.cta.shared::cta.b64 p, [%1], %2;"
                 " selp.b32 %0,1,0,p; }" : "=r"(done) : "r"(a), "r"(parity) : "memory");
    if (!done) {
        asm volatile("{ .reg .pred P1; WL%=:"
                     " mbarrier.try_wait.parity.acquire.cta.shared::cta.b64 P1, [%0], %1, 0x989680;"
                     " @P1 bra.uni WD%=; bra.uni WL%=; WD%=: }"
                     :: "r"(a), "r"(parity) : "memory");
    }
}
__device__ __forceinline__ void bulk_g2s(uint32_t dst, const void* src, uint32_t bytes,
                                         uint32_t mbar) {
    asm volatile("cp.async.bulk.shared::cta.global.mbarrier::complete_tx::bytes"
                 " [%0], [%1], %2, [%3];"
                 :: "r"(dst), "l"(src), "r"(bytes), "r"(mbar) : "memory");
}
__device__ __forceinline__ void tc_alloc(uint32_t smem_dst, uint32_t ncols) {
    asm volatile("tcgen05.alloc.cta_group::1.sync.aligned.shared::cta.b32 [%0], %1;"
                 :: "r"(smem_dst), "r"(ncols) : "memory");
}
__device__ __forceinline__ void tc_dealloc(uint32_t tmem, uint32_t ncols) {
    asm volatile("tcgen05.dealloc.cta_group::1.sync.aligned.b32 %0, %1;" :: "r"(tmem), "r"(ncols));
}
__device__ __forceinline__ void tc_relinquish() {
    asm volatile("tcgen05.relinquish_alloc_permit.cta_group::1.sync.aligned;");
}
__device__ __forceinline__ void tc_commit(uint32_t mbar) {
    asm volatile("tcgen05.commit.cta_group::1.mbarrier::arrive::one.shared::cluster.b64 [%0];"
                 :: "r"(mbar) : "memory");
}
__device__ __forceinline__ void mma_f16_ss(uint32_t d, uint64_t ad, uint64_t bd,
                                           uint32_t idesc, bool acc) {
    uint32_t en = acc ? 1u : 0u;
    asm volatile("{ .reg .pred p; setp.ne.u32 p, %4, 0;"
                 " tcgen05.mma.cta_group::1.kind::f16 [%0], %1, %2, %3, {%5,%5,%5,%5}, p; }"
                 :: "r"(d), "l"(ad), "l"(bd), "r"(idesc), "r"(en), "r"(0u) : "memory");
}
#define TC_LD_X32(r, addr) \
    asm volatile("tcgen05.ld.sync.aligned.32x32b.x32.b32 " \
        "{%0,%1,%2,%3,%4,%5,%6,%7,%8,%9,%10,%11,%12,%13,%14,%15," \
        "%16,%17,%18,%19,%20,%21,%22,%23,%24,%25,%26,%27,%28,%29,%30,%31}, [%32];" \
        : "=r"((r)[0]),"=r"((r)[1]),"=r"((r)[2]),"=r"((r)[3]),"=r"((r)[4]),"=r"((r)[5]), \
          "=r"((r)[6]),"=r"((r)[7]),"=r"((r)[8]),"=r"((r)[9]),"=r"((r)[10]),"=r"((r)[11]), \
          "=r"((r)[12]),"=r"((r)[13]),"=r"((r)[14]),"=r"((r)[15]),"=r"((r)[16]),"=r"((r)[17]), \
          "=r"((r)[18]),"=r"((r)[19]),"=r"((r)[20]),"=r"((r)[21]),"=r"((r)[22]),"=r"((r)[23]), \
          "=r"((r)[24]),"=r"((r)[25]),"=r"((r)[26]),"=r"((r)[27]),"=r"((r)[28]),"=r"((r)[29]), \
          "=r"((r)[30]),"=r"((r)[31]) : "r"(addr))
#define TC_WAIT_LD()  asm volatile("tcgen05.wait::ld.sync.aligned;" ::: "memory")
#define TC_FENCE_AFTER()  asm volatile("tcgen05.fence::after_thread_sync;" ::: "memory")
#define TC_FENCE_BEFORE() asm volatile("tcgen05.fence::before_thread_sync;" ::: "memory")
#endif // HAS_TCGEN05

// ---------------- prep: colscale + cosh/sinh(2 rc b), block per column -------
__global__ void prep_kernel(const float* __restrict__ w, const float* __restrict__ bias,
                            const float* __restrict__ c_ptr, int IN, int OUT) {
    int o = blockIdx.x;
    float s = 0.f;
    for (int i = threadIdx.x; i < IN; i += blockDim.x) {
        float v = w[(size_t)i * OUT + o];
        s = fmaf(v, v, s);
    }
    float tot = block_reduce_sum(s);
    if (threadIdx.x == 0) {
        g_colscale[o] = 1.0f / fmaxf(sqrtf(tot), 1e-15f);
        float rc = sqrtf(c_ptr[0]);
        float d = 2.0f * rc * bias[o];
        g_coshb[o] = coshf(d);
        g_sinhb[o] = sinhf(d);
    }
}

// ---------------- w -> transposed, scaled, bf16 split, SW64 tile-major -------
__global__ void convert_w_kernel(const float* __restrict__ w, int IN, int OUT) {
    __shared__ float t[32][33];
    int n0 = blockIdx.x * 32, k0 = blockIdx.y * 32;
    int tx = threadIdx.x, ty = threadIdx.y;
    t[ty][tx] = w[(size_t)(k0 + ty) * OUT + n0 + tx];   // t[k_local][n_local]
    __syncthreads();
    if (tx < 4) {
        int n = n0 + ty;
        float cs = g_colscale[n];
        uint32_t hi4[4], lo4[4];
        #pragma unroll
        for (int p = 0; p < 4; ++p) {
            float a = t[tx * 8 + p * 2 + 0][ty] * cs;
            float b = t[tx * 8 + p * 2 + 1][ty] * cs;
            __nv_bfloat16 ha = __float2bfloat16(a), hb = __float2bfloat16(b);
            float ra = a - __bfloat162float(ha), rb = b - __bfloat162float(hb);
            hi4[p] = ((uint32_t)__bfloat16_as_ushort(hb) << 16) | __bfloat16_as_ushort(ha);
            lo4[p] = pack_bf16x2(ra, rb);
        }
        int nb = n >> 7;
        size_t base = ((size_t)(nb * 32 + blockIdx.y)) * B_TILE
                    + SW64((uint32_t)((n & 127) * 64 + tx * 16));
        *(uint4*)(g_whi_t + base) = make_uint4(hi4[0], hi4[1], hi4[2], hi4[3]);
        *(uint4*)(g_wlo_t + base) = make_uint4(lo4[0], lo4[1], lo4[2], lo4[3]);
    }
}

// ---------------- x -> bf16 hi/lo SW64 tile-major, fused cx2 -----------------
__global__ void convert_x_kernel(const float* __restrict__ x,
                                 const float* __restrict__ c_ptr, int IN) {
    int row = blockIdx.x;
    int t = threadIdx.x;                 // 128 threads, 8 elements each
    if (t < 8) g_ysq_part[(size_t)row * 8 + t] = 0.f;
    const float4* xr = (const float4*)(x + (size_t)row * IN) + t * 2;
    float4 v0 = xr[0], v1 = xr[1];
    float s = v0.x*v0.x + v0.y*v0.y + v0.z*v0.z + v0.w*v0.w
            + v1.x*v1.x + v1.y*v1.y + v1.z*v1.z + v1.w*v1.w;
    float e[8] = {v0.x, v0.y, v0.z, v0.w, v1.x, v1.y, v1.z, v1.w};
    uint32_t hi4[4], lo4[4];
    #pragma unroll
    for (int p = 0; p < 4; ++p) {
        float a = e[p*2], b = e[p*2+1];
        __nv_bfloat16 ha = __float2bfloat16(a), hb = __float2bfloat16(b);
        float ra = a - __bfloat162float(ha), rb = b - __bfloat162float(hb);
        hi4[p] = ((uint32_t)__bfloat16_as_ushort(hb) << 16) | __bfloat16_as_ushort(ha);
        lo4[p] = pack_bf16x2(ra, rb);
    }
    int kc = t >> 2, g = t & 3;
    int rb = row >> 7, r = row & 127;
    size_t base = ((size_t)(rb * 32 + kc)) * A_TILE
                + SW64((uint32_t)(r * 64 + g * 16));
    *(uint4*)(g_xhi_t + base) = make_uint4(hi4[0], hi4[1], hi4[2], hi4[3]);
    *(uint4*)(g_xlo_t + base) = make_uint4(lo4[0], lo4[1], lo4[2], lo4[3]);
    float tot = block_reduce_sum(s);
    if (threadIdx.x == 0) g_cx2[row] = c_ptr[0] * tot;
}

// ---------------- GEMM + fused Poincare epilogue -----------------------------
#define MT 128
#define NT 128
// idesc: F32 out, BF16 a/b, N=128, M=128
#define IDESC ((1u<<4) | (1u<<7) | (1u<<10) | ((NT/8u)<<17) | (8u<<24))

#define OFF_TMEM 0u
#define OFF_MBF  8u                         // full barriers: 8,16,24
#define OFF_MBE  32u                        // empty barriers: 32,40,48
#define OFF_PAR  1024u                      // 3 * NT floats = 1536 B
#define OFF_T    4096u
#define STAGE    (A_TILE + B_TILE)          // 16 KB
#define NSTAGE   3
#define SMEM_BYTES (OFF_T + NSTAGE * STAGE) // 53248

__global__ __launch_bounds__(128, 4)
void gemm_tc_kernel(const float* __restrict__ X, const float* __restrict__ W,
                    const float* __restrict__ wgp, const float* __restrict__ c_ptr,
                    float* __restrict__ out, int Nrows, int IN, int OUT) {
    extern __shared__ char smem[];
#if HAS_TCGEN05
    const uint32_t sb = smem_u32(smem);
    const int tid = threadIdx.x;
    const int wid = tid >> 5, lane = tid & 31;
    const int brow = blockIdx.y * MT, bcol = blockIdx.x * NT;
    const int nchunk = 96;                   // 3 segments x 32 chunks (KC=32)

    if (wid == 0) { tc_alloc(sb + OFF_TMEM, 128); tc_relinquish(); }
    if (tid == 0) {
        #pragma unroll
        for (int s = 0; s < NSTAGE; ++s) {
            mbar_init(sb + OFF_MBF + 8u * s, 1);
            mbar_init(sb + OFF_MBE + 8u * s, 1);
        }
    }
    float* chb = (float*)(smem + OFF_PAR);
    float* shb = chb + NT;
    float* g2s = shb + NT;
    if (tid < NT) {
        int o = bcol + tid;
        chb[tid] = g_coshb[o];
        shb[tid] = g_sinhb[o];
        g2s[tid] = 2.0f * wgp[o];
    }
    __syncthreads();
    uint32_t tmem;
    asm volatile("ld.shared.b32 %0, [%1];" : "=r"(tmem) : "r"(sb + OFF_TMEM));

    if (tid == 0) {
        // -------- producer: bulk loads, prefetch distance 3 ------------------
        auto srcA = [&](int c) -> const uint8_t* {
            int seg = c >> 5, kc = c & 31;
            const uint8_t* p = (seg == 2) ? g_xlo_t : g_xhi_t;
            return p + ((size_t)(blockIdx.y * 32 + kc)) * A_TILE;
        };
        auto srcB = [&](int c) -> const uint8_t* {
            int seg = c >> 5, kc = c & 31;
            const uint8_t* p = (seg == 1) ? g_wlo_t : g_whi_t;
            return p + ((size_t)(blockIdx.x * 32 + kc)) * B_TILE;
        };
        for (int c = 0; c < nchunk; ++c) {
            const int s = c % 3;
            if (c >= 3) {
                // stage s previously held chunk c-3; wait its MMAs drained
                // (commit index (c/3)-1 on empty[s] -> parity ((c/3)-1)&1)
                mbar_wait(sb + OFF_MBE + 8u * (uint32_t)s,
                          (uint32_t)(((c / 3) - 1) & 1));
            }
            uint32_t fb = sb + OFF_MBF + 8u * (uint32_t)s;
            uint32_t base = sb + OFF_T + (uint32_t)s * STAGE;
            mbar_expect_tx(fb, STAGE);
            bulk_g2s(base, srcA(c), A_TILE, fb);
            bulk_g2s(base + A_TILE, srcB(c), B_TILE, fb);
        }
    } else if (tid == 32) {
        // -------- consumer: MMA issue + commits -------------------------------
        for (int c = 0; c < nchunk; ++c) {
            const int s = c % 3;
            mbar_wait(sb + OFF_MBF + 8u * (uint32_t)s, (uint32_t)((c / 3) & 1));
            const uint32_t base = sb + OFF_T + (uint32_t)s * STAGE;
            uint64_t ad = make_desc64(base);
            uint64_t bd = make_desc64(base + A_TILE);
            mma_f16_ss(tmem, ad,     bd,     IDESC, c > 0);
            mma_f16_ss(tmem, ad + 2, bd + 2, IDESC, true);
            tc_commit(sb + OFF_MBE + 8u * (uint32_t)s);
        }
        // final commits: 32 per stage -> last commit index 31 -> parity 1
        mbar_wait(sb + OFF_MBE + 0, 1);
        mbar_wait(sb + OFF_MBE + 8, 1);
        mbar_wait(sb + OFF_MBE + 16, 1);
    }
    __syncthreads();
    TC_FENCE_AFTER();

    // ---- epilogue: 4 warps, each owns 32 of this CTA's 128 rows, 128 cols ---
    const float rc = sqrtf(c_ptr[0]);
    const float invrc = 1.0f / rc;
    const int row = brow + wid * 32 + lane;
    const float cx2 = g_cx2[row];
    const float invd = 1.0f / fmaxf(1.0f - cx2, 1e-15f);
    const float onep = 1.0f + cx2;
    const float two_rc = 2.0f * rc;
    float ysq = 0.f;

    #pragma unroll
    for (int cc = 0; cc < 2; ++cc) {
        const int cb = cc * 64;
        uint32_t d[64];
        TC_LD_X32(d, tmem + cb);
        TC_LD_X32(d + 32, tmem + cb + 32);
        TC_WAIT_LD();
        float* orow = out + (size_t)row * OUT + bcol + cb;
        #pragma unroll
        for (int j = 0; j < 64; j += 4) {
            float yv[4];
            #pragma unroll
            for (int q = 0; q < 4; ++q) {
                int col = cb + j + q;
                float dot = __uint_as_float(d[j + q]);
                float num = fmaf(two_rc * dot, chb[col], -onep * shb[col]);
                float u = num * invd;
                // sinh(g*asinh(u)) = sign(u)*(t^g - t^-g)/2, t = sqrt(u^2+1)+|u|
                float sq = sqrtf(fmaf(u, u, 1.0f));
                float t  = sq + fabsf(u);
                float lt = __logf(t);
                float p  = __expf(g2s[col] * lt);
                float mag = (p - __fdividef(1.0f, p)) * 0.5f * invrc;
                float y = copysignf(mag, u);
                ysq = fmaf(y, y, ysq);
                yv[q] = y;
            }
            *(float4*)(orow + j) = make_float4(yv[0], yv[1], yv[2], yv[3]);
        }
    }
    g_ysq_part[(size_t)row * 8 + blockIdx.x] = ysq;

    TC_FENCE_BEFORE();
    __syncthreads();
    if (wid == 0) tc_dealloc(tmem, 128);

#else  // ------------- SIMT fallback (non-'a' PTX stage; never runs on GB300) -
    float (*As)[128] = (float(*)[128])(smem);
    float (*Bs)[128] = (float(*)[128])(smem + 16 * 128 * 4);

    const int tid = threadIdx.x;               // 128 threads
    const int brow = blockIdx.y * MT;
    const int bcol = blockIdx.x * NT;
    const float cval = c_ptr[0];
    const float rc = sqrtf(cval);
    const float invrc = 1.0f / rc;
    const int tx = tid & 15, ty = tid >> 4;     // 16 col-groups x 8 row-groups

    float acc[16][8];
    #pragma unroll
    for (int i = 0; i < 16; ++i)
        #pragma unroll
        for (int j = 0; j < 8; ++j) acc[i][j] = 0.f;

    for (int kt = 0; kt < IN; kt += 16) {
        #pragma unroll
        for (int l = 0; l < 4; ++l) {
            int idx = tid + l * 128;
            int r = idx >> 2, c4 = (idx & 3) << 2;
            float4 v = *(const float4*)(X + (size_t)(brow + r) * IN + kt + c4);
            As[c4 + 0][r] = v.x; As[c4 + 1][r] = v.y;
            As[c4 + 2][r] = v.z; As[c4 + 3][r] = v.w;
        }
        #pragma unroll
        for (int l = 0; l < 4; ++l) {
            int idx = tid + l * 128;
            int r = idx >> 5, c4 = (idx & 31) << 2;
            if (c4 < 128)
                *(float4*)(&Bs[r][c4]) =
                    *(const float4*)(W + (size_t)(kt + r) * OUT + bcol + c4);
        }
        __syncthreads();
        #pragma unroll
        for (int k = 0; k < 16; ++k) {
            float a[16], b[8];
            #pragma unroll
            for (int q = 0; q < 16; ++q) a[q] = As[k][ty * 16 + q];
            #pragma unroll
            for (int q = 0; q < 8; ++q) b[q] = Bs[k][tx * 8 + q];
            #pragma unroll
            for (int i = 0; i < 16; ++i)
                #pragma unroll
                for (int j = 0; j < 8; ++j)
                    acc[i][j] = fmaf(a[i], b[j], acc[i][j]);
        }
        __syncthreads();
    }
    #pragma unroll
    for (int i = 0; i < 16; ++i) {
        int n = brow + ty * 16 + i;
        float cx2 = g_cx2[n];
        float invd = 1.0f / fmaxf(1.0f - cx2, 1e-15f);
        float onep = 1.0f + cx2;
        float y[8];
        float ysq = 0.f;
        #pragma unroll
        for (int j = 0; j < 8; ++j) {
            int o = bcol + tx * 8 + j;
            float num = 2.0f * rc * acc[i][j] * g_colscale[o] * g_coshb[o]
                        - onep * g_sinhb[o];
            float a = 2.0f * wgp[o] * asinhf(num * invd);
            y[j] = sinhf(a) * invrc;
            ysq = fmaf(y[j], y[j], ysq);
        }
        atomicAdd(&g_ysq_part[(size_t)n * 8 + blockIdx.x], ysq);
        float* orow = out + (size_t)n * OUT + bcol + tx * 8;
        *(float4*)(orow)     = make_float4(y[0], y[1], y[2], y[3]);
        *(float4*)(orow + 4) = make_float4(y[4], y[5], y[6], y[7]);
    }
#endif
}

// ---------------- rescale: gyro-half map + ball projection -------------------
__global__ void rescale_kernel(float* __restrict__ out,
                               const float* __restrict__ c_ptr, int OUT) {
    int row = blockIdx.x;
    float tot = 0.f;
    #pragma unroll
    for (int i = 0; i < 8; ++i) tot += g_ysq_part[(size_t)row * 8 + i];
    float c = c_ptr[0];
    float denom = 1.0f + sqrtf(1.0f + c * tot);
    float scale = 1.0f / denom;
    float norm = fmaxf(sqrtf(tot) * scale, 1e-15f);
    float kk = -c;
    float maxnorm = (1.0f - 0.004f) * rsqrtf(fmaxf(fabsf(kk), 1e-15f));
    if (!(kk < 0.f)) maxnorm = 1e15f;
    if (norm > maxnorm) scale *= maxnorm / norm;

    float4* yr = (float4*)(out + (size_t)row * OUT);
    int n4 = OUT >> 2;
    for (int i = threadIdx.x; i < n4; i += blockDim.x) {
        float4 v = yr[i];
        v.x *= scale; v.y *= scale; v.z *= scale; v.w *= scale;
        yr[i] = v;
    }
}

// ---------------------------------------------------------------------------
extern "C" void kernel_launch(void* const* d_in, const int* in_sizes, int n_in,
                              void* d_out, int out_size) {
    const float* x    = (const float*)d_in[0];
    const float* w    = (const float*)d_in[1];
    const float* wg   = (const float*)d_in[2];
    const float* bias = (const float*)d_in[3];
    const float* c    = (const float*)d_in[4];
    float* out = (float*)d_out;

    int OUT = in_sizes[2];
    int IN  = in_sizes[1] / OUT;
    int N   = in_sizes[0] / IN;

    static int smem_set = 0;
    if (!smem_set) {
        cudaFuncSetAttribute(gemm_tc_kernel, cudaFuncAttributeMaxDynamicSharedMemorySize,
                             SMEM_BYTES);
        smem_set = 1;
    }

    prep_kernel<<<OUT, 256>>>(w, bias, c, IN, OUT);
    convert_w_kernel<<<dim3(OUT / 32, IN / 32), dim3(32, 32)>>>(w, IN, OUT);
    convert_x_kernel<<<N, 128>>>(x, c, IN);
    dim3 grid(OUT / NT, N / MT);              // (8, 256) = 2048 CTAs
    gemm_tc_kernel<<<grid, 128, SMEM_BYTES>>>(x, w, wg, c, out, N, IN, OUT);
    rescale_kernel<<<N, 256>>>(out, c, OUT);
}

// round 15
// speedup vs baseline: 1.8351x; 1.0712x over previous
#include <cuda_runtime.h>
#include <cuda_bf16.h>
#include <math.h>
#include <stdint.h>

// ---------------------------------------------------------------------------
// PoincareLinear via tcgen05 bf16 split GEMM (sm_103a) + SIMT fallback body.
//   dot = x_hi@w_hi + x_lo@w_hi + x_hi@w_lo   (dropped lo*lo ~ 2^-18)
//   R15: per K-chunk of 16, load {xh,xl} and {wh,wl} pairs ONCE (2x 8KB bulk
//   copies from combined blobs) and issue 3 MMAs reusing SMEM -> 33% fewer
//   bytes than the 3-segment schedule. SW32 swizzle (32B rows). 4 CTAs/SM,
//   128x128 tile, 3 stages x 16KB, warp-specialized producer/consumer.
// ---------------------------------------------------------------------------

#if defined(__CUDA_ARCH_FEAT_SM103_ALL) || defined(__CUDA_ARCH_FEAT_SM100_ALL) || \
    defined(__CUDA_ARCH_SPECIFIC__) || defined(__CUDA_ARCH_FAMILY_SPECIFIC__)
#define HAS_TCGEN05 1
#else
#define HAS_TCGEN05 0
#endif

#define N_MAX   32768
#define IN_MAX  1024
#define OUT_MAX 1024
#define SUBTILE 4096u                // 128 rows x 32 B (KC=16, one precision)
#define PAIR    8192u                // [hi 4KB][lo 4KB]

// combined blobs, tile-major, pre-SW32-swizzled:
//   X: pair(rb,kc) at (rb*64+kc)*8KB, rb = row>>7, kc = k>>4; hi@+0, lo@+4096
//   W: pair(nb,kc) at (nb*64+kc)*8KB, nb = n>>7
__device__ uint8_t g_x_t[(size_t)N_MAX * IN_MAX * 4];
__device__ uint8_t g_w_t[(size_t)OUT_MAX * IN_MAX * 4];
__device__ float g_colscale[OUT_MAX];
__device__ float g_coshb[OUT_MAX];
__device__ float g_sinhb[OUT_MAX];
__device__ float g_cx2[N_MAX];
__device__ float g_ysq_part[(size_t)N_MAX * 8];

// SW32 descriptor: layout=6, version=1 (Blackwell), SBO=16 (8 rows x 32B /16),
// LBO=1 (16B inner stride).
constexpr uint64_t kSmemDescBaseSW32 =
    (uint64_t(6) << 61) | (uint64_t(1) << 46) | (uint64_t(16) << 32) | (uint64_t(1) << 16);

// ---------------- generic helpers -------------------------------------------
__device__ __forceinline__ uint32_t smem_u32(const void* p) {
    uint32_t a;
    asm("{ .reg .u64 t; cvta.to.shared.u64 t, %1; cvt.u32.u64 %0, t; }"
        : "=r"(a) : "l"(p));
    return a;
}
#define SW32(off) ((off) ^ (((off) >> 3) & 0x10))

__device__ __forceinline__ float block_reduce_sum(float v) {
    __shared__ float red[32];
    int lane = threadIdx.x & 31, wid = threadIdx.x >> 5;
    #pragma unroll
    for (int o = 16; o > 0; o >>= 1) v += __shfl_down_sync(0xffffffff, v, o);
    if (lane == 0) red[wid] = v;
    __syncthreads();
    int nw = (blockDim.x + 31) >> 5;
    v = (threadIdx.x < nw) ? red[threadIdx.x] : 0.f;
    if (wid == 0)
        #pragma unroll
        for (int o = 16; o > 0; o >>= 1) v += __shfl_down_sync(0xffffffff, v, o);
    return v;
}

__device__ __forceinline__ uint32_t pack_bf16x2(float a, float b) {
    __nv_bfloat16 ha = __float2bfloat16(a), hb = __float2bfloat16(b);
    return ((uint32_t)__bfloat16_as_ushort(hb) << 16) | __bfloat16_as_ushort(ha);
}

#if HAS_TCGEN05
// ---------------- tcgen05 / mbarrier / bulk-copy wrappers --------------------
__device__ __forceinline__ uint64_t make_desc32(uint32_t addr) {
    return kSmemDescBaseSW32 | ((uint64_t)(addr >> 4) & 0x3FFF);
}
__device__ __forceinline__ void mbar_init(uint32_t a, uint32_t cnt) {
    asm volatile("mbarrier.init.shared.b64 [%0], %1;" :: "r"(a), "r"(cnt) : "memory");
}
__device__ __forceinline__ void mbar_expect_tx(uint32_t a, uint32_t bytes) {
    asm volatile("mbarrier.arrive.expect_tx.shared.b64 _, [%0], %1;"
                 :: "r"(a), "r"(bytes) : "memory");
}
__device__ __forceinline__ void mbar_wait(uint32_t a, uint32_t parity) {
    uint32_t done;
    asm volatile("{ .reg .pred p; mbarrier.try_wait.parity.acquire.cta.shared::cta.b64 p, [%1], %2;"
                 " selp.b32 %0,1,0,p; }" : "=r"(done) : "r"(a), "r"(parity) : "memory");
    if (!done) {
        asm volatile("{ .reg .pred P1; WL%=:"
                     " mbarrier.try_wait.parity.acquire.cta.shared::cta.b64 P1, [%0], %1, 0x989680;"
                     " @P1 bra.uni WD%=; bra.uni WL%=; WD%=: }"
                     :: "r"(a), "r"(parity) : "memory");
    }
}
__device__ __forceinline__ void bulk_g2s(uint32_t dst, const void* src, uint32_t bytes,
                                         uint32_t mbar) {
    asm volatile("cp.async.bulk.shared::cta.global.mbarrier::complete_tx::bytes"
                 " [%0], [%1], %2, [%3];"
                 :: "r"(dst), "l"(src), "r"(bytes), "r"(mbar) : "memory");
}
__device__ __forceinline__ void tc_alloc(uint32_t smem_dst, uint32_t ncols) {
    asm volatile("tcgen05.alloc.cta_group::1.sync.aligned.shared::cta.b32 [%0], %1;"
                 :: "r"(smem_dst), "r"(ncols) : "memory");
}
__device__ __forceinline__ void tc_dealloc(uint32_t tmem, uint32_t ncols) {
    asm volatile("tcgen05.dealloc.cta_group::1.sync.aligned.b32 %0, %1;" :: "r"(tmem), "r"(ncols));
}
__device__ __forceinline__ void tc_relinquish() {
    asm volatile("tcgen05.relinquish_alloc_permit.cta_group::1.sync.aligned;");
}
__device__ __forceinline__ void tc_commit(uint32_t mbar) {
    asm volatile("tcgen05.commit.cta_group::1.mbarrier::arrive::one.shared::cluster.b64 [%0];"
                 :: "r"(mbar) : "memory");
}
__device__ __forceinline__ void mma_f16_ss(uint32_t d, uint64_t ad, uint64_t bd,
                                           uint32_t idesc, bool acc) {
    uint32_t en = acc ? 1u : 0u;
    asm volatile("{ .reg .pred p; setp.ne.u32 p, %4, 0;"
                 " tcgen05.mma.cta_group::1.kind::f16 [%0], %1, %2, %3, {%5,%5,%5,%5}, p; }"
                 :: "r"(d), "l"(ad), "l"(bd), "r"(idesc), "r"(en), "r"(0u) : "memory");
}
#define TC_LD_X32(r, addr) \
    asm volatile("tcgen05.ld.sync.aligned.32x32b.x32.b32 " \
        "{%0,%1,%2,%3,%4,%5,%6,%7,%8,%9,%10,%11,%12,%13,%14,%15," \
        "%16,%17,%18,%19,%20,%21,%22,%23,%24,%25,%26,%27,%28,%29,%30,%31}, [%32];" \
        : "=r"((r)[0]),"=r"((r)[1]),"=r"((r)[2]),"=r"((r)[3]),"=r"((r)[4]),"=r"((r)[5]), \
          "=r"((r)[6]),"=r"((r)[7]),"=r"((r)[8]),"=r"((r)[9]),"=r"((r)[10]),"=r"((r)[11]), \
          "=r"((r)[12]),"=r"((r)[13]),"=r"((r)[14]),"=r"((r)[15]),"=r"((r)[16]),"=r"((r)[17]), \
          "=r"((r)[18]),"=r"((r)[19]),"=r"((r)[20]),"=r"((r)[21]),"=r"((r)[22]),"=r"((r)[23]), \
          "=r"((r)[24]),"=r"((r)[25]),"=r"((r)[26]),"=r"((r)[27]),"=r"((r)[28]),"=r"((r)[29]), \
          "=r"((r)[30]),"=r"((r)[31]) : "r"(addr))
#define TC_WAIT_LD()  asm volatile("tcgen05.wait::ld.sync.aligned;" ::: "memory")
#define TC_FENCE_AFTER()  asm volatile("tcgen05.fence::after_thread_sync;" ::: "memory")
#define TC_FENCE_BEFORE() asm volatile("tcgen05.fence::before_thread_sync;" ::: "memory")
#endif // HAS_TCGEN05

// ---------------- prep: colscale + cosh/sinh(2 rc b), block per column -------
__global__ void prep_kernel(const float* __restrict__ w, const float* __restrict__ bias,
                            const float* __restrict__ c_ptr, int IN, int OUT) {
    int o = blockIdx.x;
    float s = 0.f;
    for (int i = threadIdx.x; i < IN; i += blockDim.x) {
        float v = w[(size_t)i * OUT + o];
        s = fmaf(v, v, s);
    }
    float tot = block_reduce_sum(s);
    if (threadIdx.x == 0) {
        g_colscale[o] = 1.0f / fmaxf(sqrtf(tot), 1e-15f);
        float rc = sqrtf(c_ptr[0]);
        float d = 2.0f * rc * bias[o];
        g_coshb[o] = coshf(d);
        g_sinhb[o] = sinhf(d);
    }
}

// ---------------- w -> transposed, scaled, bf16 split, SW32 pair blobs -------
__global__ void convert_w_kernel(const float* __restrict__ w, int IN, int OUT) {
    __shared__ float t[32][33];
    int n0 = blockIdx.x * 32, k0 = blockIdx.y * 32;
    int tx = threadIdx.x, ty = threadIdx.y;
    t[ty][tx] = w[(size_t)(k0 + ty) * OUT + n0 + tx];   // t[k_local][n_local]
    __syncthreads();
    if (tx < 4) {
        int n = n0 + ty;
        float cs = g_colscale[n];
        uint32_t hi4[4], lo4[4];
        #pragma unroll
        for (int p = 0; p < 4; ++p) {
            float a = t[tx * 8 + p * 2 + 0][ty] * cs;
            float b = t[tx * 8 + p * 2 + 1][ty] * cs;
            __nv_bfloat16 ha = __float2bfloat16(a), hb = __float2bfloat16(b);
            float ra = a - __bfloat162float(ha), rb = b - __bfloat162float(hb);
            hi4[p] = ((uint32_t)__bfloat16_as_ushort(hb) << 16) | __bfloat16_as_ushort(ha);
            lo4[p] = pack_bf16x2(ra, rb);
        }
        // k = k0 + tx*8 -> kc16 = (k0>>4) + (tx>>1), 16B group = tx&1
        int kc = (k0 >> 4) + (tx >> 1);
        int g = tx & 1;
        int nb = n >> 7;
        size_t base = ((size_t)(nb * 64 + kc)) * PAIR
                    + SW32((uint32_t)((n & 127) * 32 + g * 16));
        *(uint4*)(g_w_t + base) = make_uint4(hi4[0], hi4[1], hi4[2], hi4[3]);
        *(uint4*)(g_w_t + base + SUBTILE) = make_uint4(lo4[0], lo4[1], lo4[2], lo4[3]);
    }
}

// ---------------- x -> bf16 hi/lo SW32 pair blobs, fused cx2 -----------------
__global__ void convert_x_kernel(const float* __restrict__ x,
                                 const float* __restrict__ c_ptr, int IN) {
    int row = blockIdx.x;
    int t = threadIdx.x;                 // 128 threads, 8 elements each
    if (t < 8) g_ysq_part[(size_t)row * 8 + t] = 0.f;
    const float4* xr = (const float4*)(x + (size_t)row * IN) + t * 2;
    float4 v0 = xr[0], v1 = xr[1];
    float s = v0.x*v0.x + v0.y*v0.y + v0.z*v0.z + v0.w*v0.w
            + v1.x*v1.x + v1.y*v1.y + v1.z*v1.z + v1.w*v1.w;
    float e[8] = {v0.x, v0.y, v0.z, v0.w, v1.x, v1.y, v1.z, v1.w};
    uint32_t hi4[4], lo4[4];
    #pragma unroll
    for (int p = 0; p < 4; ++p) {
        float a = e[p*2], b = e[p*2+1];
        __nv_bfloat16 ha = __float2bfloat16(a), hb = __float2bfloat16(b);
        float ra = a - __bfloat162float(ha), rb = b - __bfloat162float(hb);
        hi4[p] = ((uint32_t)__bfloat16_as_ushort(hb) << 16) | __bfloat16_as_ushort(ha);
        lo4[p] = pack_bf16x2(ra, rb);
    }
    // thread t: k in [t*8, t*8+8) -> kc16 = t>>1, 16B group = t&1
    int kc = t >> 1, g = t & 1;
    int rb = row >> 7, r = row & 127;
    size_t base = ((size_t)(rb * 64 + kc)) * PAIR
                + SW32((uint32_t)(r * 32 + g * 16));
    *(uint4*)(g_x_t + base) = make_uint4(hi4[0], hi4[1], hi4[2], hi4[3]);
    *(uint4*)(g_x_t + base + SUBTILE) = make_uint4(lo4[0], lo4[1], lo4[2], lo4[3]);
    float tot = block_reduce_sum(s);
    if (threadIdx.x == 0) g_cx2[row] = c_ptr[0] * tot;
}

// ---------------- GEMM + fused Poincare epilogue -----------------------------
#define MT 128
#define NT 128
// idesc: F32 out, BF16 a/b, N=128, M=128
#define IDESC ((1u<<4) | (1u<<7) | (1u<<10) | ((NT/8u)<<17) | (8u<<24))

#define OFF_TMEM 0u
#define OFF_MBF  8u                         // full barriers: 8,16,24
#define OFF_MBE  32u                        // empty barriers: 32,40,48
#define OFF_PAR  1024u                      // 3 * NT floats = 1536 B
#define OFF_T    4096u
#define STAGE    (2u * PAIR)                // 16 KB: [xh][xl][wh][wl]
#define NSTAGE   3
#define SMEM_BYTES (OFF_T + NSTAGE * STAGE) // 53248

__global__ __launch_bounds__(128, 4)
void gemm_tc_kernel(const float* __restrict__ X, const float* __restrict__ W,
                    const float* __restrict__ wgp, const float* __restrict__ c_ptr,
                    float* __restrict__ out, int Nrows, int IN, int OUT) {
    extern __shared__ char smem[];
#if HAS_TCGEN05
    const uint32_t sb = smem_u32(smem);
    const int tid = threadIdx.x;
    const int wid = tid >> 5, lane = tid & 31;
    const int brow = blockIdx.y * MT, bcol = blockIdx.x * NT;
    const int nchunk = IN >> 4;              // 64 chunks of K=16

    if (wid == 0) { tc_alloc(sb + OFF_TMEM, 128); tc_relinquish(); }
    if (tid == 0) {
        #pragma unroll
        for (int s = 0; s < NSTAGE; ++s) {
            mbar_init(sb + OFF_MBF + 8u * s, 1);
            mbar_init(sb + OFF_MBE + 8u * s, 1);
        }
    }
    float* chb = (float*)(smem + OFF_PAR);
    float* shb = chb + NT;
    float* g2s = shb + NT;
    if (tid < NT) {
        int o = bcol + tid;
        chb[tid] = g_coshb[o];
        shb[tid] = g_sinhb[o];
        g2s[tid] = 2.0f * wgp[o];
    }
    __syncthreads();
    uint32_t tmem;
    asm volatile("ld.shared.b32 %0, [%1];" : "=r"(tmem) : "r"(sb + OFF_TMEM));

    if (tid == 0) {
        // -------- producer: one 8KB x-pair + one 8KB w-pair per chunk --------
        const uint8_t* xblob = g_x_t + ((size_t)blockIdx.y * 64) * PAIR;
        const uint8_t* wblob = g_w_t + ((size_t)blockIdx.x * 64) * PAIR;
        for (int c = 0; c < nchunk; ++c) {
            const int s = c % 3;
            if (c >= 3) {
                mbar_wait(sb + OFF_MBE + 8u * (uint32_t)s,
                          (uint32_t)(((c / 3) - 1) & 1));
            }
            uint32_t fb = sb + OFF_MBF + 8u * (uint32_t)s;
            uint32_t base = sb + OFF_T + (uint32_t)s * STAGE;
            mbar_expect_tx(fb, STAGE);
            bulk_g2s(base, xblob + (size_t)c * PAIR, PAIR, fb);
            bulk_g2s(base + PAIR, wblob + (size_t)c * PAIR, PAIR, fb);
        }
    } else if (tid == 32) {
        // -------- consumer: 3 MMAs per chunk (xh@wh, xl@wh, xh@wl) -----------
        for (int c = 0; c < nchunk; ++c) {
            const int s = c % 3;
            mbar_wait(sb + OFF_MBF + 8u * (uint32_t)s, (uint32_t)((c / 3) & 1));
            const uint32_t base = sb + OFF_T + (uint32_t)s * STAGE;
            uint64_t xh = make_desc32(base);
            uint64_t xl = make_desc32(base + SUBTILE);
            uint64_t wh = make_desc32(base + PAIR);
            uint64_t wl = make_desc32(base + PAIR + SUBTILE);
            mma_f16_ss(tmem, xh, wh, IDESC, c > 0);
            mma_f16_ss(tmem, xl, wh, IDESC, true);
            mma_f16_ss(tmem, xh, wl, IDESC, true);
            tc_commit(sb + OFF_MBE + 8u * (uint32_t)s);
        }
        // final drain: last commit per stage (nchunk=64):
        //   s0: 22 commits -> idx 21 -> parity 1 ; s1/s2: 21 -> idx 20 -> 0
        mbar_wait(sb + OFF_MBE + 0, 1);
        mbar_wait(sb + OFF_MBE + 8, 0);
        mbar_wait(sb + OFF_MBE + 16, 0);
    }
    __syncthreads();
    TC_FENCE_AFTER();

    // ---- epilogue: 4 warps, each owns 32 of this CTA's 128 rows, 128 cols ---
    const float rc = sqrtf(c_ptr[0]);
    const float invrc = 1.0f / rc;
    const int row = brow + wid * 32 + lane;
    const float cx2 = g_cx2[row];
    const float invd = 1.0f / fmaxf(1.0f - cx2, 1e-15f);
    const float onep = 1.0f + cx2;
    const float two_rc = 2.0f * rc;
    float ysq = 0.f;

    #pragma unroll
    for (int cc = 0; cc < 2; ++cc) {
        const int cb = cc * 64;
        uint32_t d[64];
        TC_LD_X32(d, tmem + cb);
        TC_LD_X32(d + 32, tmem + cb + 32);
        TC_WAIT_LD();
        float* orow = out + (size_t)row * OUT + bcol + cb;
        #pragma unroll
        for (int j = 0; j < 64; j += 4) {
            float yv[4];
            #pragma unroll
            for (int q = 0; q < 4; ++q) {
                int col = cb + j + q;
                float dot = __uint_as_float(d[j + q]);
                float num = fmaf(two_rc * dot, chb[col], -onep * shb[col]);
                float u = num * invd;
                // sinh(g*asinh(u)) = sign(u)*(t^g - t^-g)/2, t = sqrt(u^2+1)+|u|
                float sq = sqrtf(fmaf(u, u, 1.0f));
                float t  = sq + fabsf(u);
                float lt = __logf(t);
                float p  = __expf(g2s[col] * lt);
                float mag = (p - __fdividef(1.0f, p)) * 0.5f * invrc;
                float y = copysignf(mag, u);
                ysq = fmaf(y, y, ysq);
                yv[q] = y;
            }
            *(float4*)(orow + j) = make_float4(yv[0], yv[1], yv[2], yv[3]);
        }
    }
    g_ysq_part[(size_t)row * 8 + blockIdx.x] = ysq;

    TC_FENCE_BEFORE();
    __syncthreads();
    if (wid == 0) tc_dealloc(tmem, 128);

#else  // ------------- SIMT fallback (non-'a' PTX stage; never runs on GB300) -
    float (*As)[128] = (float(*)[128])(smem);
    float (*Bs)[128] = (float(*)[128])(smem + 16 * 128 * 4);

    const int tid = threadIdx.x;               // 128 threads
    const int brow = blockIdx.y * MT;
    const int bcol = blockIdx.x * NT;
    const float cval = c_ptr[0];
    const float rc = sqrtf(cval);
    const float invrc = 1.0f / rc;
    const int tx = tid & 15, ty = tid >> 4;     // 16 col-groups x 8 row-groups

    float acc[16][8];
    #pragma unroll
    for (int i = 0; i < 16; ++i)
        #pragma unroll
        for (int j = 0; j < 8; ++j) acc[i][j] = 0.f;

    for (int kt = 0; kt < IN; kt += 16) {
        #pragma unroll
        for (int l = 0; l < 4; ++l) {
            int idx = tid + l * 128;
            int r = idx >> 2, c4 = (idx & 3) << 2;
            float4 v = *(const float4*)(X + (size_t)(brow + r) * IN + kt + c4);
            As[c4 + 0][r] = v.x; As[c4 + 1][r] = v.y;
            As[c4 + 2][r] = v.z; As[c4 + 3][r] = v.w;
        }
        #pragma unroll
        for (int l = 0; l < 4; ++l) {
            int idx = tid + l * 128;
            int r = idx >> 5, c4 = (idx & 31) << 2;
            if (c4 < 128)
                *(float4*)(&Bs[r][c4]) =
                    *(const float4*)(W + (size_t)(kt + r) * OUT + bcol + c4);
        }
        __syncthreads();
        #pragma unroll
        for (int k = 0; k < 16; ++k) {
            float a[16], b[8];
            #pragma unroll
            for (int q = 0; q < 16; ++q) a[q] = As[k][ty * 16 + q];
            #pragma unroll
            for (int q = 0; q < 8; ++q) b[q] = Bs[k][tx * 8 + q];
            #pragma unroll
            for (int i = 0; i < 16; ++i)
                #pragma unroll
                for (int j = 0; j < 8; ++j)
                    acc[i][j] = fmaf(a[i], b[j], acc[i][j]);
        }
        __syncthreads();
    }
    #pragma unroll
    for (int i = 0; i < 16; ++i) {
        int n = brow + ty * 16 + i;
        float cx2 = g_cx2[n];
        float invd = 1.0f / fmaxf(1.0f - cx2, 1e-15f);
        float onep = 1.0f + cx2;
        float y[8];
        float ysq = 0.f;
        #pragma unroll
        for (int j = 0; j < 8; ++j) {
            int o = bcol + tx * 8 + j;
            float num = 2.0f * rc * acc[i][j] * g_colscale[o] * g_coshb[o]
                        - onep * g_sinhb[o];
            float a = 2.0f * wgp[o] * asinhf(num * invd);
            y[j] = sinhf(a) * invrc;
            ysq = fmaf(y[j], y[j], ysq);
        }
        atomicAdd(&g_ysq_part[(size_t)n * 8 + blockIdx.x], ysq);
        float* orow = out + (size_t)n * OUT + bcol + tx * 8;
        *(float4*)(orow)     = make_float4(y[0], y[1], y[2], y[3]);
        *(float4*)(orow + 4) = make_float4(y[4], y[5], y[6], y[7]);
    }
#endif
}

// ---------------- rescale: gyro-half map + ball projection -------------------
__global__ void rescale_kernel(float* __restrict__ out,
                               const float* __restrict__ c_ptr, int OUT) {
    int row = blockIdx.x;
    float tot = 0.f;
    #pragma unroll
    for (int i = 0; i < 8; ++i) tot += g_ysq_part[(size_t)row * 8 + i];
    float c = c_ptr[0];
    float denom = 1.0f + sqrtf(1.0f + c * tot);
    float scale = 1.0f / denom;
    float norm = fmaxf(sqrtf(tot) * scale, 1e-15f);
    float kk = -c;
    float maxnorm = (1.0f - 0.004f) * rsqrtf(fmaxf(fabsf(kk), 1e-15f));
    if (!(kk < 0.f)) maxnorm = 1e15f;
    if (norm > maxnorm) scale *= maxnorm / norm;

    float4* yr = (float4*)(out + (size_t)row * OUT);
    int n4 = OUT >> 2;
    for (int i = threadIdx.x; i < n4; i += blockDim.x) {
        float4 v = yr[i];
        v.x *= scale; v.y *= scale; v.z *= scale; v.w *= scale;
        yr[i] = v;
    }
}

// ---------------------------------------------------------------------------
extern "C" void kernel_launch(void* const* d_in, const int* in_sizes, int n_in,
                              void* d_out, int out_size) {
    const float* x    = (const float*)d_in[0];
    const float* w    = (const float*)d_in[1];
    const float* wg   = (const float*)d_in[2];
    const float* bias = (const float*)d_in[3];
    const float* c    = (const float*)d_in[4];
    float* out = (float*)d_out;

    int OUT = in_sizes[2];
    int IN  = in_sizes[1] / OUT;
    int N   = in_sizes[0] / IN;

    static int smem_set = 0;
    if (!smem_set) {
        cudaFuncSetAttribute(gemm_tc_kernel, cudaFuncAttributeMaxDynamicSharedMemorySize,
                             SMEM_BYTES);
        smem_set = 1;
    }

    prep_kernel<<<OUT, 256>>>(w, bias, c, IN, OUT);
    convert_w_kernel<<<dim3(OUT / 32, IN / 32), dim3(32, 32)>>>(w, IN, OUT);
    convert_x_kernel<<<N, 128>>>(x, c, IN);
    dim3 grid(OUT / NT, N / MT);              // (8, 256) = 2048 CTAs
    gemm_tc_kernel<<<grid, 128, SMEM_BYTES>>>(x, w, wg, c, out, N, IN, OUT);
    rescale_kernel<<<N, 256>>>(out, c, OUT);
}

// round 16
// speedup vs baseline: 1.8362x; 1.0006x over previous
#include <cuda_runtime.h>
#include <cuda_bf16.h>
#include <math.h>
#include <stdint.h>

// ---------------------------------------------------------------------------
// PoincareLinear via tcgen05 bf16 split GEMM (sm_103a) + SIMT fallback body.
//   dot = x_hi@w_hi + x_lo@w_hi + x_hi@w_lo   (dropped lo*lo ~ 2^-18)
//   R16: R15 + W-pair multicast across cluster(1,2,1). Per chunk each rank
//   loads its x-pair (8KB local) + one 4KB w-subtile multicast to both CTAs
//   (rank0: wh, rank1: wl). Empty barriers count 2, commits multicast.
//   SW32 swizzle, 4 CTAs/SM, 128x128 tile, 3 stages x 16KB, warp-specialized.
// ---------------------------------------------------------------------------

#if defined(__CUDA_ARCH_FEAT_SM103_ALL) || defined(__CUDA_ARCH_FEAT_SM100_ALL) || \
    defined(__CUDA_ARCH_SPECIFIC__) || defined(__CUDA_ARCH_FAMILY_SPECIFIC__)
#define HAS_TCGEN05 1
#else
#define HAS_TCGEN05 0
#endif

#define N_MAX   32768
#define IN_MAX  1024
#define OUT_MAX 1024
#define SUBTILE 4096u                // 128 rows x 32 B (KC=16, one precision)
#define PAIR    8192u                // [hi 4KB][lo 4KB]

// combined blobs, tile-major, pre-SW32-swizzled:
//   X: pair(rb,kc) at (rb*64+kc)*8KB, rb = row>>7, kc = k>>4; hi@+0, lo@+4096
//   W: pair(nb,kc) at (nb*64+kc)*8KB, nb = n>>7
__device__ uint8_t g_x_t[(size_t)N_MAX * IN_MAX * 4];
__device__ uint8_t g_w_t[(size_t)OUT_MAX * IN_MAX * 4];
__device__ float g_colscale[OUT_MAX];
__device__ float g_coshb[OUT_MAX];
__device__ float g_sinhb[OUT_MAX];
__device__ float g_cx2[N_MAX];
__device__ float g_ysq_part[(size_t)N_MAX * 8];

// SW32 descriptor: layout=6, version=1 (Blackwell), SBO=16, LBO=1.
constexpr uint64_t kSmemDescBaseSW32 =
    (uint64_t(6) << 61) | (uint64_t(1) << 46) | (uint64_t(16) << 32) | (uint64_t(1) << 16);

// ---------------- generic helpers -------------------------------------------
__device__ __forceinline__ uint32_t smem_u32(const void* p) {
    uint32_t a;
    asm("{ .reg .u64 t; cvta.to.shared.u64 t, %1; cvt.u32.u64 %0, t; }"
        : "=r"(a) : "l"(p));
    return a;
}
#define SW32(off) ((off) ^ (((off) >> 3) & 0x10))

__device__ __forceinline__ float block_reduce_sum(float v) {
    __shared__ float red[32];
    int lane = threadIdx.x & 31, wid = threadIdx.x >> 5;
    #pragma unroll
    for (int o = 16; o > 0; o >>= 1) v += __shfl_down_sync(0xffffffff, v, o);
    if (lane == 0) red[wid] = v;
    __syncthreads();
    int nw = (blockDim.x + 31) >> 5;
    v = (threadIdx.x < nw) ? red[threadIdx.x] : 0.f;
    if (wid == 0)
        #pragma unroll
        for (int o = 16; o > 0; o >>= 1) v += __shfl_down_sync(0xffffffff, v, o);
    return v;
}

__device__ __forceinline__ uint32_t pack_bf16x2(float a, float b) {
    __nv_bfloat16 ha = __float2bfloat16(a), hb = __float2bfloat16(b);
    return ((uint32_t)__bfloat16_as_ushort(hb) << 16) | __bfloat16_as_ushort(ha);
}

#if HAS_TCGEN05
// ---------------- tcgen05 / mbarrier / bulk-copy wrappers --------------------
__device__ __forceinline__ uint64_t make_desc32(uint32_t addr) {
    return kSmemDescBaseSW32 | ((uint64_t)(addr >> 4) & 0x3FFF);
}
__device__ __forceinline__ void mbar_init(uint32_t a, uint32_t cnt) {
    asm volatile("mbarrier.init.shared.b64 [%0], %1;" :: "r"(a), "r"(cnt) : "memory");
}
__device__ __forceinline__ void mbar_expect_tx(uint32_t a, uint32_t bytes) {
    asm volatile("mbarrier.arrive.expect_tx.shared.b64 _, [%0], %1;"
                 :: "r"(a), "r"(bytes) : "memory");
}
__device__ __forceinline__ void mbar_wait(uint32_t a, uint32_t parity) {
    uint32_t done;
    asm volatile("{ .reg .pred p; mbarrier.try_wait.parity.acquire.cta.shared::cta.b64 p, [%1], %2;"
                 " selp.b32 %0,1,0,p; }" : "=r"(done) : "r"(a), "r"(parity) : "memory");
    if (!done) {
        asm volatile("{ .reg .pred P1; WL%=:"
                     " mbarrier.try_wait.parity.acquire.cta.shared::cta.b64 P1, [%0], %1, 0x989680;"
                     " @P1 bra.uni WD%=; bra.uni WL%=; WD%=: }"
                     :: "r"(a), "r"(parity) : "memory");
    }
}
__device__ __forceinline__ void bulk_g2s(uint32_t dst, const void* src, uint32_t bytes,
                                         uint32_t mbar) {
    asm volatile("cp.async.bulk.shared::cta.global.mbarrier::complete_tx::bytes"
                 " [%0], [%1], %2, [%3];"
                 :: "r"(dst), "l"(src), "r"(bytes), "r"(mbar) : "memory");
}
__device__ __forceinline__ void bulk_g2s_mc(uint32_t dst, const void* src, uint32_t bytes,
                                            uint32_t mbar, uint16_t mask) {
    asm volatile("cp.async.bulk.shared::cluster.global.mbarrier::complete_tx::bytes"
                 ".multicast::cluster [%0], [%1], %2, [%3], %4;"
                 :: "r"(dst), "l"(src), "r"(bytes), "r"(mbar), "h"(mask) : "memory");
}
__device__ __forceinline__ void tc_alloc(uint32_t smem_dst, uint32_t ncols) {
    asm volatile("tcgen05.alloc.cta_group::1.sync.aligned.shared::cta.b32 [%0], %1;"
                 :: "r"(smem_dst), "r"(ncols) : "memory");
}
__device__ __forceinline__ void tc_dealloc(uint32_t tmem, uint32_t ncols) {
    asm volatile("tcgen05.dealloc.cta_group::1.sync.aligned.b32 %0, %1;" :: "r"(tmem), "r"(ncols));
}
__device__ __forceinline__ void tc_relinquish() {
    asm volatile("tcgen05.relinquish_alloc_permit.cta_group::1.sync.aligned;");
}
__device__ __forceinline__ void tc_commit_mc(uint32_t mbar, uint16_t mask) {
    asm volatile("tcgen05.commit.cta_group::1.mbarrier::arrive::one.shared::cluster"
                 ".multicast::cluster.b64 [%0], %1;"
                 :: "r"(mbar), "h"(mask) : "memory");
}
__device__ __forceinline__ void mma_f16_ss(uint32_t d, uint64_t ad, uint64_t bd,
                                           uint32_t idesc, bool acc) {
    uint32_t en = acc ? 1u : 0u;
    asm volatile("{ .reg .pred p; setp.ne.u32 p, %4, 0;"
                 " tcgen05.mma.cta_group::1.kind::f16 [%0], %1, %2, %3, {%5,%5,%5,%5}, p; }"
                 :: "r"(d), "l"(ad), "l"(bd), "r"(idesc), "r"(en), "r"(0u) : "memory");
}
#define TC_LD_X32(r, addr) \
    asm volatile("tcgen05.ld.sync.aligned.32x32b.x32.b32 " \
        "{%0,%1,%2,%3,%4,%5,%6,%7,%8,%9,%10,%11,%12,%13,%14,%15," \
        "%16,%17,%18,%19,%20,%21,%22,%23,%24,%25,%26,%27,%28,%29,%30,%31}, [%32];" \
        : "=r"((r)[0]),"=r"((r)[1]),"=r"((r)[2]),"=r"((r)[3]),"=r"((r)[4]),"=r"((r)[5]), \
          "=r"((r)[6]),"=r"((r)[7]),"=r"((r)[8]),"=r"((r)[9]),"=r"((r)[10]),"=r"((r)[11]), \
          "=r"((r)[12]),"=r"((r)[13]),"=r"((r)[14]),"=r"((r)[15]),"=r"((r)[16]),"=r"((r)[17]), \
          "=r"((r)[18]),"=r"((r)[19]),"=r"((r)[20]),"=r"((r)[21]),"=r"((r)[22]),"=r"((r)[23]), \
          "=r"((r)[24]),"=r"((r)[25]),"=r"((r)[26]),"=r"((r)[27]),"=r"((r)[28]),"=r"((r)[29]), \
          "=r"((r)[30]),"=r"((r)[31]) : "r"(addr))
#define TC_WAIT_LD()  asm volatile("tcgen05.wait::ld.sync.aligned;" ::: "memory")
#define TC_FENCE_AFTER()  asm volatile("tcgen05.fence::after_thread_sync;" ::: "memory")
#define TC_FENCE_BEFORE() asm volatile("tcgen05.fence::before_thread_sync;" ::: "memory")
#define CLUSTER_SYNC() do { \
    asm volatile("barrier.cluster.arrive.aligned;" ::: "memory"); \
    asm volatile("barrier.cluster.wait.aligned;" ::: "memory"); } while (0)
#endif // HAS_TCGEN05

// ---------------- prep: colscale + cosh/sinh(2 rc b), block per column -------
__global__ void prep_kernel(const float* __restrict__ w, const float* __restrict__ bias,
                            const float* __restrict__ c_ptr, int IN, int OUT) {
    int o = blockIdx.x;
    float s = 0.f;
    for (int i = threadIdx.x; i < IN; i += blockDim.x) {
        float v = w[(size_t)i * OUT + o];
        s = fmaf(v, v, s);
    }
    float tot = block_reduce_sum(s);
    if (threadIdx.x == 0) {
        g_colscale[o] = 1.0f / fmaxf(sqrtf(tot), 1e-15f);
        float rc = sqrtf(c_ptr[0]);
        float d = 2.0f * rc * bias[o];
        g_coshb[o] = coshf(d);
        g_sinhb[o] = sinhf(d);
    }
}

// ---------------- w -> transposed, scaled, bf16 split, SW32 pair blobs -------
__global__ void convert_w_kernel(const float* __restrict__ w, int IN, int OUT) {
    __shared__ float t[32][33];
    int n0 = blockIdx.x * 32, k0 = blockIdx.y * 32;
    int tx = threadIdx.x, ty = threadIdx.y;
    t[ty][tx] = w[(size_t)(k0 + ty) * OUT + n0 + tx];   // t[k_local][n_local]
    __syncthreads();
    if (tx < 4) {
        int n = n0 + ty;
        float cs = g_colscale[n];
        uint32_t hi4[4], lo4[4];
        #pragma unroll
        for (int p = 0; p < 4; ++p) {
            float a = t[tx * 8 + p * 2 + 0][ty] * cs;
            float b = t[tx * 8 + p * 2 + 1][ty] * cs;
            __nv_bfloat16 ha = __float2bfloat16(a), hb = __float2bfloat16(b);
            float ra = a - __bfloat162float(ha), rb = b - __bfloat162float(hb);
            hi4[p] = ((uint32_t)__bfloat16_as_ushort(hb) << 16) | __bfloat16_as_ushort(ha);
            lo4[p] = pack_bf16x2(ra, rb);
        }
        int kc = (k0 >> 4) + (tx >> 1);
        int g = tx & 1;
        int nb = n >> 7;
        size_t base = ((size_t)(nb * 64 + kc)) * PAIR
                    + SW32((uint32_t)((n & 127) * 32 + g * 16));
        *(uint4*)(g_w_t + base) = make_uint4(hi4[0], hi4[1], hi4[2], hi4[3]);
        *(uint4*)(g_w_t + base + SUBTILE) = make_uint4(lo4[0], lo4[1], lo4[2], lo4[3]);
    }
}

// ---------------- x -> bf16 hi/lo SW32 pair blobs, fused cx2 -----------------
__global__ void convert_x_kernel(const float* __restrict__ x,
                                 const float* __restrict__ c_ptr, int IN) {
    int row = blockIdx.x;
    int t = threadIdx.x;                 // 128 threads, 8 elements each
    if (t < 8) g_ysq_part[(size_t)row * 8 + t] = 0.f;
    const float4* xr = (const float4*)(x + (size_t)row * IN) + t * 2;
    float4 v0 = xr[0], v1 = xr[1];
    float s = v0.x*v0.x + v0.y*v0.y + v0.z*v0.z + v0.w*v0.w
            + v1.x*v1.x + v1.y*v1.y + v1.z*v1.z + v1.w*v1.w;
    float e[8] = {v0.x, v0.y, v0.z, v0.w, v1.x, v1.y, v1.z, v1.w};
    uint32_t hi4[4], lo4[4];
    #pragma unroll
    for (int p = 0; p < 4; ++p) {
        float a = e[p*2], b = e[p*2+1];
        __nv_bfloat16 ha = __float2bfloat16(a), hb = __float2bfloat16(b);
        float ra = a - __bfloat162float(ha), rb = b - __bfloat162float(hb);
        hi4[p] = ((uint32_t)__bfloat16_as_ushort(hb) << 16) | __bfloat16_as_ushort(ha);
        lo4[p] = pack_bf16x2(ra, rb);
    }
    int kc = t >> 1, g = t & 1;
    int rb = row >> 7, r = row & 127;
    size_t base = ((size_t)(rb * 64 + kc)) * PAIR
                + SW32((uint32_t)(r * 32 + g * 16));
    *(uint4*)(g_x_t + base) = make_uint4(hi4[0], hi4[1], hi4[2], hi4[3]);
    *(uint4*)(g_x_t + base + SUBTILE) = make_uint4(lo4[0], lo4[1], lo4[2], lo4[3]);
    float tot = block_reduce_sum(s);
    if (threadIdx.x == 0) g_cx2[row] = c_ptr[0] * tot;
}

// ---------------- GEMM + fused Poincare epilogue -----------------------------
#define MT 128
#define NT 128
// idesc: F32 out, BF16 a/b, N=128, M=128
#define IDESC ((1u<<4) | (1u<<7) | (1u<<10) | ((NT/8u)<<17) | (8u<<24))

#define OFF_TMEM 0u
#define OFF_MBF  8u                         // full barriers: 8,16,24
#define OFF_MBE  32u                        // empty barriers: 32,40,48
#define OFF_PAR  1024u                      // 3 * NT floats = 1536 B
#define OFF_T    4096u
#define STAGE    (2u * PAIR)                // 16 KB: [xh][xl][wh][wl]
#define NSTAGE   3
#define SMEM_BYTES (OFF_T + NSTAGE * STAGE) // 53248

__global__ __launch_bounds__(128, 4) __cluster_dims__(1, 2, 1)
void gemm_tc_kernel(const float* __restrict__ X, const float* __restrict__ W,
                    const float* __restrict__ wgp, const float* __restrict__ c_ptr,
                    float* __restrict__ out, int Nrows, int IN, int OUT) {
    extern __shared__ char smem[];
#if HAS_TCGEN05
    const uint32_t sb = smem_u32(smem);
    const int tid = threadIdx.x;
    const int wid = tid >> 5, lane = tid & 31;
    const int brow = blockIdx.y * MT, bcol = blockIdx.x * NT;
    const int rank = (int)(blockIdx.y & 1);
    const int nchunk = IN >> 4;              // 64 chunks of K=16

    if (wid == 0) { tc_alloc(sb + OFF_TMEM, 128); tc_relinquish(); }
    if (tid == 0) {
        #pragma unroll
        for (int s = 0; s < NSTAGE; ++s) {
            mbar_init(sb + OFF_MBF + 8u * s, 1);
            mbar_init(sb + OFF_MBE + 8u * s, 2);   // both CTAs' commits
        }
    }
    float* chb = (float*)(smem + OFF_PAR);
    float* shb = chb + NT;
    float* g2s = shb + NT;
    if (tid < NT) {
        int o = bcol + tid;
        chb[tid] = g_coshb[o];
        shb[tid] = g_sinhb[o];
        g2s[tid] = 2.0f * wgp[o];
    }
    __syncthreads();
    CLUSTER_SYNC();            // all barriers init'd before any multicast lands
    uint32_t tmem;
    asm volatile("ld.shared.b32 %0, [%1];" : "=r"(tmem) : "r"(sb + OFF_TMEM));

    if (tid == 0) {
        // -------- producer: x-pair local (8KB) + one w-subtile multicast -----
        const uint8_t* xblob = g_x_t + ((size_t)blockIdx.y * 64) * PAIR;
        const uint8_t* wblob = g_w_t + ((size_t)blockIdx.x * 64) * PAIR
                             + (uint32_t)rank * SUBTILE;   // wh (r0) / wl (r1)
        const uint32_t wdst_off = PAIR + (uint32_t)rank * SUBTILE;
        for (int c = 0; c < nchunk; ++c) {
            const int s = c % 3;
            if (c >= 3) {
                mbar_wait(sb + OFF_MBE + 8u * (uint32_t)s,
                          (uint32_t)(((c / 3) - 1) & 1));
            }
            uint32_t fb = sb + OFF_MBF + 8u * (uint32_t)s;
            uint32_t base = sb + OFF_T + (uint32_t)s * STAGE;
            mbar_expect_tx(fb, STAGE);        // 8K x + 4K wh + 4K wl received
            bulk_g2s(base, xblob + (size_t)c * PAIR, PAIR, fb);
            bulk_g2s_mc(base + wdst_off, wblob + (size_t)c * PAIR, SUBTILE, fb, 0x3);
        }
    } else if (tid == 32) {
        // -------- consumer: 3 MMAs per chunk, multicast commit ---------------
        for (int c = 0; c < nchunk; ++c) {
            const int s = c % 3;
            mbar_wait(sb + OFF_MBF + 8u * (uint32_t)s, (uint32_t)((c / 3) & 1));
            const uint32_t base = sb + OFF_T + (uint32_t)s * STAGE;
            uint64_t xh = make_desc32(base);
            uint64_t xl = make_desc32(base + SUBTILE);
            uint64_t wh = make_desc32(base + PAIR);
            uint64_t wl = make_desc32(base + PAIR + SUBTILE);
            mma_f16_ss(tmem, xh, wh, IDESC, c > 0);
            mma_f16_ss(tmem, xl, wh, IDESC, true);
            mma_f16_ss(tmem, xh, wl, IDESC, true);
            tc_commit_mc(sb + OFF_MBE + 8u * (uint32_t)s, 0x3);
        }
        // final drain (local): s0 parity 1, s1/s2 parity 0 (as R15)
        mbar_wait(sb + OFF_MBE + 0, 1);
        mbar_wait(sb + OFF_MBE + 8, 0);
        mbar_wait(sb + OFF_MBE + 16, 0);
    }
    __syncthreads();
    TC_FENCE_AFTER();

    // ---- epilogue: 4 warps, each owns 32 of this CTA's 128 rows, 128 cols ---
    const float rc = sqrtf(c_ptr[0]);
    const float invrc = 1.0f / rc;
    const int row = brow + wid * 32 + lane;
    const float cx2 = g_cx2[row];
    const float invd = 1.0f / fmaxf(1.0f - cx2, 1e-15f);
    const float onep = 1.0f + cx2;
    const float two_rc = 2.0f * rc;
    float ysq = 0.f;

    #pragma unroll
    for (int cc = 0; cc < 2; ++cc) {
        const int cb = cc * 64;
        uint32_t d[64];
        TC_LD_X32(d, tmem + cb);
        TC_LD_X32(d + 32, tmem + cb + 32);
        TC_WAIT_LD();
        float* orow = out + (size_t)row * OUT + bcol + cb;
        #pragma unroll
        for (int j = 0; j < 64; j += 4) {
            float yv[4];
            #pragma unroll
            for (int q = 0; q < 4; ++q) {
                int col = cb + j + q;
                float dot = __uint_as_float(d[j + q]);
                float num = fmaf(two_rc * dot, chb[col], -onep * shb[col]);
                float u = num * invd;
                // sinh(g*asinh(u)) = sign(u)*(t^g - t^-g)/2, t = sqrt(u^2+1)+|u|
                float sq = sqrtf(fmaf(u, u, 1.0f));
                float t  = sq + fabsf(u);
                float lt = __logf(t);
                float p  = __expf(g2s[col] * lt);
                float mag = (p - __fdividef(1.0f, p)) * 0.5f * invrc;
                float y = copysignf(mag, u);
                ysq = fmaf(y, y, ysq);
                yv[q] = y;
            }
            *(float4*)(orow + j) = make_float4(yv[0], yv[1], yv[2], yv[3]);
        }
    }
    g_ysq_part[(size_t)row * 8 + blockIdx.x] = ysq;

    TC_FENCE_BEFORE();
    __syncthreads();
    if (wid == 0) tc_dealloc(tmem, 128);
    CLUSTER_SYNC();            // peer multicasts fully drained before exit

#else  // ------------- SIMT fallback (non-'a' PTX stage; never runs on GB300) -
    float (*As)[128] = (float(*)[128])(smem);
    float (*Bs)[128] = (float(*)[128])(smem + 16 * 128 * 4);

    const int tid = threadIdx.x;               // 128 threads
    const int brow = blockIdx.y * MT;
    const int bcol = blockIdx.x * NT;
    const float cval = c_ptr[0];
    const float rc = sqrtf(cval);
    const float invrc = 1.0f / rc;
    const int tx = tid & 15, ty = tid >> 4;     // 16 col-groups x 8 row-groups

    float acc[16][8];
    #pragma unroll
    for (int i = 0; i < 16; ++i)
        #pragma unroll
        for (int j = 0; j < 8; ++j) acc[i][j] = 0.f;

    for (int kt = 0; kt < IN; kt += 16) {
        #pragma unroll
        for (int l = 0; l < 4; ++l) {
            int idx = tid + l * 128;
            int r = idx >> 2, c4 = (idx & 3) << 2;
            float4 v = *(const float4*)(X + (size_t)(brow + r) * IN + kt + c4);
            As[c4 + 0][r] = v.x; As[c4 + 1][r] = v.y;
            As[c4 + 2][r] = v.z; As[c4 + 3][r] = v.w;
        }
        #pragma unroll
        for (int l = 0; l < 4; ++l) {
            int idx = tid + l * 128;
            int r = idx >> 5, c4 = (idx & 31) << 2;
            if (c4 < 128)
                *(float4*)(&Bs[r][c4]) =
                    *(const float4*)(W + (size_t)(kt + r) * OUT + bcol + c4);
        }
        __syncthreads();
        #pragma unroll
        for (int k = 0; k < 16; ++k) {
            float a[16], b[8];
            #pragma unroll
            for (int q = 0; q < 16; ++q) a[q] = As[k][ty * 16 + q];
            #pragma unroll
            for (int q = 0; q < 8; ++q) b[q] = Bs[k][tx * 8 + q];
            #pragma unroll
            for (int i = 0; i < 16; ++i)
                #pragma unroll
                for (int j = 0; j < 8; ++j)
                    acc[i][j] = fmaf(a[i], b[j], acc[i][j]);
        }
        __syncthreads();
    }
    #pragma unroll
    for (int i = 0; i < 16; ++i) {
        int n = brow + ty * 16 + i;
        float cx2 = g_cx2[n];
        float invd = 1.0f / fmaxf(1.0f - cx2, 1e-15f);
        float onep = 1.0f + cx2;
        float y[8];
        float ysq = 0.f;
        #pragma unroll
        for (int j = 0; j < 8; ++j) {
            int o = bcol + tx * 8 + j;
            float num = 2.0f * rc * acc[i][j] * g_colscale[o] * g_coshb[o]
                        - onep * g_sinhb[o];
            float a = 2.0f * wgp[o] * asinhf(num * invd);
            y[j] = sinhf(a) * invrc;
            ysq = fmaf(y[j], y[j], ysq);
        }
        atomicAdd(&g_ysq_part[(size_t)n * 8 + blockIdx.x], ysq);
        float* orow = out + (size_t)n * OUT + bcol + tx * 8;
        *(float4*)(orow)     = make_float4(y[0], y[1], y[2], y[3]);
        *(float4*)(orow + 4) = make_float4(y[4], y[5], y[6], y[7]);
    }
#endif
}

// ---------------- rescale: gyro-half map + ball projection -------------------
__global__ void rescale_kernel(float* __restrict__ out,
                               const float* __restrict__ c_ptr, int OUT) {
    int row = blockIdx.x;
    float tot = 0.f;
    #pragma unroll
    for (int i = 0; i < 8; ++i) tot += g_ysq_part[(size_t)row * 8 + i];
    float c = c_ptr[0];
    float denom = 1.0f + sqrtf(1.0f + c * tot);
    float scale = 1.0f / denom;
    float norm = fmaxf(sqrtf(tot) * scale, 1e-15f);
    float kk = -c;
    float maxnorm = (1.0f - 0.004f) * rsqrtf(fmaxf(fabsf(kk), 1e-15f));
    if (!(kk < 0.f)) maxnorm = 1e15f;
    if (norm > maxnorm) scale *= maxnorm / norm;

    float4* yr = (float4*)(out + (size_t)row * OUT);
    int n4 = OUT >> 2;
    for (int i = threadIdx.x; i < n4; i += blockDim.x) {
        float4 v = yr[i];
        v.x *= scale; v.y *= scale; v.z *= scale; v.w *= scale;
        yr[i] = v;
    }
}

// ---------------------------------------------------------------------------
extern "C" void kernel_launch(void* const* d_in, const int* in_sizes, int n_in,
                              void* d_out, int out_size) {
    const float* x    = (const float*)d_in[0];
    const float* w    = (const float*)d_in[1];
    const float* wg   = (const float*)d_in[2];
    const float* bias = (const float*)d_in[3];
    const float* c    = (const float*)d_in[4];
    float* out = (float*)d_out;

    int OUT = in_sizes[2];
    int IN  = in_sizes[1] / OUT;
    int N   = in_sizes[0] / IN;

    static int smem_set = 0;
    if (!smem_set) {
        cudaFuncSetAttribute(gemm_tc_kernel, cudaFuncAttributeMaxDynamicSharedMemorySize,
                             SMEM_BYTES);
        smem_set = 1;
    }

    prep_kernel<<<OUT, 256>>>(w, bias, c, IN, OUT);
    convert_w_kernel<<<dim3(OUT / 32, IN / 32), dim3(32, 32)>>>(w, IN, OUT);
    convert_x_kernel<<<N, 128>>>(x, c, IN);
    dim3 grid(OUT / NT, N / MT);              // (8, 256), clusters of 2 along y
    gemm_tc_kernel<<<grid, 128, SMEM_BYTES>>>(x, w, wg, c, out, N, IN, OUT);
    rescale_kernel<<<N, 256>>>(out, c, OUT);
}